// round 2
// baseline (speedup 1.0000x reference)
#include <cuda_runtime.h>
#include <cstdint>
#include <math.h>

// Problem constants
#define Bz 2
#define Sq 2048
#define Ed 1024
#define Hh 16
#define Dh 64
#define E3 3072
#define Mrows (Bz*Sq)   // 4096

// ---------------- device scratch (no allocations allowed) ----------------
__device__ __align__(16) float g_qkv[Bz * Sq * E3];   // (B*S, 3E)  ~50 MB
__device__ __align__(16) float g_ctx[Bz * Sq * Ed];   // (B*S, E)   ~17 MB
__device__ int   g_mask_mode;           // 0=u8, 1=i32, 2=f32, 3=u16

// ---------------- mask dtype detector ----------------
// Scans the first nbytes and classifies the storage by byte patterns:
//   int32 0/1      -> nonzero only at offset%4==0
//   float32 0/1.0f -> nonzero only at offsets 2,3 (bytes 0x80,0x3F)
//   1-byte 0/1     -> nonzero everywhere, all bytes in {0,1}
//   16-bit (fp16/bf16) -> spread but contains bytes not in {0,1}
__global__ void detect_mask_mode_kernel(const unsigned char* __restrict__ m,
                                        long long nbytes) {
    __shared__ int cnt[5]; // c0..c3, weird
    if (threadIdx.x < 5) cnt[threadIdx.x] = 0;
    __syncthreads();
    int local[5] = {0, 0, 0, 0, 0};
    for (long long i = threadIdx.x; i < nbytes; i += blockDim.x) {
        unsigned char v = m[i];
        if (v) {
            local[(int)(i & 3)]++;
            if (v != 1) local[4]++;
        }
    }
#pragma unroll
    for (int j = 0; j < 5; j++)
        if (local[j]) atomicAdd(&cnt[j], local[j]);
    __syncthreads();
    if (threadIdx.x == 0) {
        int c0 = cnt[0], c1 = cnt[1], c2 = cnt[2], c3 = cnt[3], weird = cnt[4];
        int mode;
        if (c1 == 0 && c2 == 0 && c3 == 0)      mode = 1;  // int32
        else if (c0 == 0 && c1 == 0)            mode = 2;  // float32
        else if (weird > 0)                     mode = 3;  // 16-bit
        else                                    mode = 0;  // bytes
        (void)c2; (void)c3;
        g_mask_mode = mode;
    }
}

// ---------------- fp32 SGEMM: C = A(MxK) * B(KxN) + bias, all row-major ----
// 128x128 block tile, BK=8, 256 threads, 8x8 per-thread micro tile.
__global__ __launch_bounds__(256, 2)
void sgemm_bias_kernel(const float* __restrict__ A,
                       const float* __restrict__ Bm,
                       const float* __restrict__ bias,
                       float* __restrict__ C,
                       int M, int N, int K) {
    __shared__ float As[8][128];   // A tile transposed: As[k][m]
    __shared__ float Bs[8][128];   // Bs[k][n]

    const int tid = threadIdx.x;
    const int bx = blockIdx.x;     // N tile
    const int by = blockIdx.y;     // M tile

    // global load mapping
    const int a_row = tid >> 1;            // 0..127
    const int a_col = (tid & 1) << 2;      // 0 or 4
    const int b_row = tid >> 5;            // 0..7
    const int b_col = (tid & 31) << 2;     // 0..124

    const float* Ag = A + (size_t)(by * 128 + a_row) * K + a_col;
    const float* Bg = Bm + (size_t)b_row * N + bx * 128 + b_col;

    // compute mapping: 8 warps as 4x2
    const int warp = tid >> 5;
    const int lane = tid & 31;
    const int warp_row = warp & 3;
    const int warp_col = warp >> 2;
    const int ty_ = lane >> 3;             // 0..3
    const int tx_ = lane & 7;              // 0..7
    const int m0 = warp_row * 32 + ty_ * 8;
    const int n0 = warp_col * 64 + tx_ * 8;

    float acc[8][8];
#pragma unroll
    for (int i = 0; i < 8; i++)
#pragma unroll
        for (int j = 0; j < 8; j++) acc[i][j] = 0.f;

    const int ksteps = K >> 3;
    for (int ks = 0; ks < ksteps; ks++) {
        float4 av = *(const float4*)Ag;   Ag += 8;
        float4 bv = *(const float4*)Bg;   Bg += (size_t)8 * N;
        __syncthreads();
        As[a_col + 0][a_row] = av.x;
        As[a_col + 1][a_row] = av.y;
        As[a_col + 2][a_row] = av.z;
        As[a_col + 3][a_row] = av.w;
        *(float4*)&Bs[b_row][b_col] = bv;
        __syncthreads();
#pragma unroll
        for (int kk = 0; kk < 8; kk++) {
            float a[8], b[8];
            *(float4*)(a)     = *(const float4*)&As[kk][m0];
            *(float4*)(a + 4) = *(const float4*)&As[kk][m0 + 4];
            *(float4*)(b)     = *(const float4*)&Bs[kk][n0];
            *(float4*)(b + 4) = *(const float4*)&Bs[kk][n0 + 4];
#pragma unroll
            for (int i = 0; i < 8; i++)
#pragma unroll
                for (int j = 0; j < 8; j++)
                    acc[i][j] += a[i] * b[j];
        }
    }

    // epilogue with bias
    const int crow = by * 128 + m0;
    const int ccol = bx * 128 + n0;
    float4 bias0 = *(const float4*)&bias[ccol];
    float4 bias1 = *(const float4*)&bias[ccol + 4];
#pragma unroll
    for (int i = 0; i < 8; i++) {
        float* cp = C + (size_t)(crow + i) * N + ccol;
        float4 r0, r1;
        r0.x = acc[i][0] + bias0.x; r0.y = acc[i][1] + bias0.y;
        r0.z = acc[i][2] + bias0.z; r0.w = acc[i][3] + bias0.w;
        r1.x = acc[i][4] + bias1.x; r1.y = acc[i][5] + bias1.y;
        r1.z = acc[i][6] + bias1.z; r1.w = acc[i][7] + bias1.w;
        *(float4*)cp       = r0;
        *(float4*)(cp + 4) = r1;
    }
}

// ---------------- flash attention with the 1e-9 mask quirk ----------------
// Grid: (S/64, B*H). Block: 256 threads (8 warps). Each warp owns 8 query rows.
#define BQ 64
#define BK 64
#define KT_LD 66   // padded row stride for transposed K tile (EVEN: float2-aligned)

__global__ __launch_bounds__(256)
void attention_kernel(const float* __restrict__ qkv,
                      const void* __restrict__ mask,
                      float* __restrict__ ctx) {
    extern __shared__ float sm[];
    float* Qs = sm;                         // [64][64]
    float* KT = Qs + BQ * Dh;               // [64][KT_LD] (KT[d][k])
    float* Vs = KT + Dh * KT_LD;            // [64][64] (Vs[k][d])
    float* Ps = Vs + BK * Dh;               // [64][64]
    unsigned char* Ms = (unsigned char*)(Ps + BQ * BK); // [64][64]

    const int qt = blockIdx.x;
    const int bh = blockIdx.y;
    const int b = bh / Hh, h = bh % Hh;
    const int tid = threadIdx.x;
    const int lane = tid & 31, warp = tid >> 5;
    const int q0 = qt * BQ;
    const int hoff = h * Dh;

    const int mode = g_mask_mode;
    const unsigned char*  m8  = (const unsigned char*)mask;
    const int*            m32 = (const int*)mask;
    const float*          mf  = (const float*)mask;
    const unsigned short* m16 = (const unsigned short*)mask;

    // load Q tile
    for (int i = tid; i < BQ * 16; i += 256) {
        int r = i >> 4, c = (i & 15) << 2;
        float4 v = *(const float4*)&qkv[((size_t)(b * Sq + q0 + r)) * E3 + hoff + c];
        *(float4*)&Qs[r * Dh + c] = v;
    }

    float mrow[8], lrow[8], acc0[8], acc1[8];
#pragma unroll
    for (int q = 0; q < 8; q++) {
        mrow[q] = -INFINITY; lrow[q] = 0.f; acc0[q] = 0.f; acc1[q] = 0.f;
    }
    const int qbase = warp * 8;

    for (int kt = 0; kt < Sq / BK; kt++) {
        const int k0 = kt * BK;
        __syncthreads();  // protect KT/Vs/Ms from previous iteration readers
        // load K (transposed) and V tiles
        for (int i = tid; i < BK * 16; i += 256) {
            int r = i >> 4, c = (i & 15) << 2;
            const size_t row = (size_t)(b * Sq + k0 + r) * E3;
            float4 kv = *(const float4*)&qkv[row + Ed + hoff + c];
            KT[(c + 0) * KT_LD + r] = kv.x;
            KT[(c + 1) * KT_LD + r] = kv.y;
            KT[(c + 2) * KT_LD + r] = kv.z;
            KT[(c + 3) * KT_LD + r] = kv.w;
            float4 vv = *(const float4*)&qkv[row + 2 * Ed + hoff + c];
            *(float4*)&Vs[r * Dh + c] = vv;
        }
        // load mask tile (mode-dispatched)
        for (int i = tid; i < (BQ * BK) / 4; i += 256) {
            int e = i << 2;
            int r = e >> 6, c = e & 63;
            size_t base = ((size_t)(b * Sq) + q0 + r) * Sq + k0 + c;
            uchar4 u;
            if (mode == 0) {
                u.x = m8[base] != 0; u.y = m8[base + 1] != 0;
                u.z = m8[base + 2] != 0; u.w = m8[base + 3] != 0;
            } else if (mode == 1) {
                u.x = m32[base] != 0; u.y = m32[base + 1] != 0;
                u.z = m32[base + 2] != 0; u.w = m32[base + 3] != 0;
            } else if (mode == 2) {
                u.x = mf[base] != 0.f; u.y = mf[base + 1] != 0.f;
                u.z = mf[base + 2] != 0.f; u.w = mf[base + 3] != 0.f;
            } else {
                u.x = m16[base] != 0; u.y = m16[base + 1] != 0;
                u.z = m16[base + 2] != 0; u.w = m16[base + 3] != 0;
            }
            *(uchar4*)&Ms[r * 64 + c] = u;
        }
        __syncthreads();

        // scores: lane owns k columns {2*lane, 2*lane+1} for warp's 8 q rows
        float s0[8], s1[8];
#pragma unroll
        for (int q = 0; q < 8; q++) { s0[q] = 0.f; s1[q] = 0.f; }
#pragma unroll 4
        for (int d = 0; d < Dh; d++) {
            float2 kv = *(const float2*)&KT[d * KT_LD + 2 * lane];
#pragma unroll
            for (int q = 0; q < 8; q++) {
                float a = Qs[(qbase + q) * Dh + d];
                s0[q] += a * kv.x;
                s1[q] += a * kv.y;
            }
        }
        // scale + mask quirk (masked -> literally 1e-9, not -inf)
#pragma unroll
        for (int q = 0; q < 8; q++) {
            unsigned char mA = Ms[(qbase + q) * 64 + 2 * lane];
            unsigned char mB = Ms[(qbase + q) * 64 + 2 * lane + 1];
            s0[q] = mA ? 1e-9f : s0[q] * 0.125f;
            s1[q] = mB ? 1e-9f : s1[q] * 0.125f;
        }
        // online softmax per row + write P
#pragma unroll
        for (int q = 0; q < 8; q++) {
            float mx = fmaxf(s0[q], s1[q]);
#pragma unroll
            for (int o = 16; o > 0; o >>= 1)
                mx = fmaxf(mx, __shfl_xor_sync(0xffffffffu, mx, o));
            float mnew = fmaxf(mrow[q], mx);
            float corr = __expf(mrow[q] - mnew);   // expf(-inf)=0 on first tile
            float p0 = __expf(s0[q] - mnew);
            float p1 = __expf(s1[q] - mnew);
            float ssum = p0 + p1;
#pragma unroll
            for (int o = 16; o > 0; o >>= 1)
                ssum += __shfl_xor_sync(0xffffffffu, ssum, o);
            lrow[q] = lrow[q] * corr + ssum;
            acc0[q] *= corr;
            acc1[q] *= corr;
            mrow[q] = mnew;
            float2 pw; pw.x = p0; pw.y = p1;
            *(float2*)&Ps[(qbase + q) * 64 + 2 * lane] = pw;
        }
        __syncwarp();
        // PV accumulate: lane owns d columns {lane, lane+32}
#pragma unroll 4
        for (int k = 0; k < BK; k++) {
            float v0 = Vs[k * Dh + lane];
            float v1 = Vs[k * Dh + lane + 32];
#pragma unroll
            for (int q = 0; q < 8; q++) {
                float p = Ps[(qbase + q) * 64 + k];
                acc0[q] += p * v0;
                acc1[q] += p * v1;
            }
        }
    }

    // epilogue: normalize and write ctx (b, s, h*64+d)
#pragma unroll
    for (int q = 0; q < 8; q++) {
        float inv = 1.f / lrow[q];
        int qg = q0 + qbase + q;
        size_t o = ((size_t)(b * Sq) + qg) * Ed + hoff;
        ctx[o + lane]      = acc0[q] * inv;
        ctx[o + lane + 32] = acc1[q] * inv;
    }
}

// ---------------- launcher ----------------
extern "C" void kernel_launch(void* const* d_in, const int* in_sizes, int n_in,
                              void* d_out, int out_size) {
    const float* x        = (const float*)d_in[0];
    const void*  amask    = d_in[1];
    const float* w_kernel = (const float*)d_in[2];
    const float* w_bias   = (const float*)d_in[3];
    const float* fc_kernel= (const float*)d_in[4];
    const float* fc_bias  = (const float*)d_in[5];
    float* out = (float*)d_out;

    float* qkv = nullptr;
    float* ctx = nullptr;
    cudaGetSymbolAddress((void**)&qkv, g_qkv);
    cudaGetSymbolAddress((void**)&ctx, g_ctx);

    // 1. mask dtype detection
    long long nscan = in_sizes[1];
    if (nscan > (1 << 20)) nscan = (1 << 20);
    detect_mask_mode_kernel<<<1, 256>>>((const unsigned char*)amask, nscan);

    // 2. QKV projection: (4096x1024)*(1024x3072)+bias
    {
        dim3 grid(E3 / 128, Mrows / 128);
        sgemm_bias_kernel<<<grid, 256>>>(x, w_kernel, w_bias, qkv,
                                         Mrows, E3, Ed);
    }

    // 3. flash attention
    {
        int smem = (BQ * Dh + Dh * KT_LD + BK * Dh + BQ * BK) * (int)sizeof(float)
                   + BQ * BK; // Ms bytes
        cudaFuncSetAttribute(attention_kernel,
                             cudaFuncAttributeMaxDynamicSharedMemorySize, smem);
        dim3 grid(Sq / BQ, Bz * Hh);
        attention_kernel<<<grid, 256, smem>>>(qkv, amask, ctx);
    }

    // 4. output projection: (4096x1024)*(1024x1024)+bias
    {
        dim3 grid(Ed / 128, Mrows / 128);
        sgemm_bias_kernel<<<grid, 256>>>(ctx, fc_kernel, fc_bias, out,
                                         Mrows, Ed, Ed);
    }
}

// round 4
// speedup vs baseline: 1.3104x; 1.3104x over previous
#include <cuda_runtime.h>
#include <cstdint>
#include <math.h>

// Problem constants
#define Bz 2
#define Sq 2048
#define Ed 1024
#define Hh 16
#define Dh 64
#define E3 3072
#define Mrows (Bz*Sq)   // 4096

// ---------------- device scratch ----------------
__device__ __align__(16) float g_qkv[Bz * Sq * E3];     // (B*S, 3E)
__device__ __align__(16) float g_ctx[Bz * Sq * Ed];     // (B*S, E), tf32-rounded
__device__ __align__(16) float g_xr [Bz * Sq * Ed];     // tf32-rounded x
__device__ __align__(16) float g_bt [E3 * Ed];          // w_kernel^T (3072x1024), rounded
__device__ __align__(16) float g_bt2[Ed * Ed];          // fc_kernel^T (1024x1024), rounded
__device__ int   g_mask_mode;

// ---------------- base-PTX helpers (NO 'a'-target features!) ----------------
__device__ __forceinline__ uint32_t smem_u32(const void* p) {
    uint32_t a;
    asm("{ .reg .u64 t; cvta.to.shared.u64 t, %1; cvt.u32.u64 %0, t; }" : "=r"(a) : "l"(p));
    return a;
}
__device__ __forceinline__ float to_tf32(float x) {
    float r; asm("cvt.rna.tf32.f32 %0, %1;" : "=f"(r) : "f"(x)); return r;
}
__device__ __forceinline__ void cp_async16(uint32_t dst, const void* src) {
    asm volatile("cp.async.cg.shared.global [%0], [%1], 16;" :: "r"(dst), "l"(src));
}
#define CP_COMMIT() asm volatile("cp.async.commit_group;" ::: "memory")
#define CP_WAIT(n)  asm volatile("cp.async.wait_group %0;" :: "n"(n) : "memory")

// D(16x8,f32) += A(16x8,tf32,row) * B(8x8,tf32,col)
__device__ __forceinline__ void mma_tf32(float* d, const uint32_t* a, const uint32_t* b) {
    asm volatile("mma.sync.aligned.m16n8k8.row.col.f32.tf32.tf32.f32 "
                 "{%0,%1,%2,%3}, {%4,%5,%6,%7}, {%8,%9}, {%0,%1,%2,%3};"
                 : "+f"(d[0]), "+f"(d[1]), "+f"(d[2]), "+f"(d[3])
                 : "r"(a[0]), "r"(a[1]), "r"(a[2]), "r"(a[3]),
                   "r"(b[0]), "r"(b[1]));
}

// ---------------- mask dtype detector (proven) ----------------
__global__ void detect_mask_mode_kernel(const unsigned char* __restrict__ m, long long nbytes) {
    __shared__ int cnt[5];
    if (threadIdx.x < 5) cnt[threadIdx.x] = 0;
    __syncthreads();
    int local[5] = {0, 0, 0, 0, 0};
    for (long long i = threadIdx.x; i < nbytes; i += blockDim.x) {
        unsigned char v = m[i];
        if (v) { local[(int)(i & 3)]++; if (v != 1) local[4]++; }
    }
#pragma unroll
    for (int j = 0; j < 5; j++) if (local[j]) atomicAdd(&cnt[j], local[j]);
    __syncthreads();
    if (threadIdx.x == 0) {
        int c0 = cnt[0], c1 = cnt[1], weird = cnt[4];
        int mode;
        if (c1 == 0 && cnt[2] == 0 && cnt[3] == 0) mode = 1;
        else if (c0 == 0 && c1 == 0)               mode = 2;
        else if (weird > 0)                        mode = 3;
        else                                       mode = 0;
        g_mask_mode = mode;
    }
}

// ---------------- tf32 pre-rounding utilities ----------------
__global__ void round_copy_kernel(const float4* __restrict__ in, float4* __restrict__ out, int n4) {
    int i = blockIdx.x * blockDim.x + threadIdx.x;
    if (i < n4) {
        float4 v = in[i];
        v.x = to_tf32(v.x); v.y = to_tf32(v.y); v.z = to_tf32(v.z); v.w = to_tf32(v.w);
        out[i] = v;
    }
}
// out[n*K+k] = rna(in[k*N+n])
__global__ void transpose_round_kernel(const float* __restrict__ in, float* __restrict__ out,
                                       int K, int N) {
    __shared__ float t[32][33];
    int n0 = blockIdx.x * 32, k0 = blockIdx.y * 32;
    for (int i = threadIdx.y; i < 32; i += 8)
        t[i][threadIdx.x] = to_tf32(in[(size_t)(k0 + i) * N + n0 + threadIdx.x]);
    __syncthreads();
    for (int i = threadIdx.y; i < 32; i += 8)
        out[(size_t)(n0 + i) * K + k0 + threadIdx.x] = t[threadIdx.x][i];
}

// ---------------- tf32 mma.sync GEMM: C = A * Bt^T + bias ----------------
// A: (M,K) row-major tf32-rounded. Bt: (N,K) row-major tf32-rounded. K=1024.
// CTA tile 128x128, 8 warps (4x2), warp tile 32x64 = 2x8 m16n8k8 atoms.
// BK=16, double-buffered cp.async. SMEM rows padded to 20 floats
// (16B-aligned rows AND conflict-free fragment LDS: (m*20+k)%32 covers all banks).
#define APAD 20
#define BKg 16

__global__ __launch_bounds__(256, 1)
void tf32_mma_gemm(const float* __restrict__ A, const float* __restrict__ Bt,
                   const float* __restrict__ bias, float* __restrict__ C,
                   int N, int K)
{
    __shared__ float As[2][128 * APAD];
    __shared__ float Bs[2][128 * APAD];

    const int tid = threadIdx.x;
    const int warp = tid >> 5, lane = tid & 31;
    const int gid = lane >> 2;          // 0..7
    const int tig = lane & 3;           // 0..3
    const int m0 = blockIdx.y * 128, n0 = blockIdx.x * 128;
    const int wm0 = (warp & 3) * 32;    // warp m offset in tile
    const int wn0 = (warp >> 2) * 64;   // warp n offset in tile

    const float* Ab = A + (size_t)m0 * K;
    const float* Bb = Bt + (size_t)n0 * K;

    float acc[2][8][4];
#pragma unroll
    for (int i = 0; i < 2; i++)
#pragma unroll
        for (int j = 0; j < 8; j++)
#pragma unroll
            for (int r = 0; r < 4; r++) acc[i][j][r] = 0.f;

    // per-thread load coords: 512 float4 chunks per matrix per stage, 2 each
    const int c0g = tid, c1g = 256 + tid;
    const int lm0 = c0g >> 2, lk0 = (c0g & 3) << 2;
    const int lm1 = c1g >> 2, lk1 = (c1g & 3) << 2;

    const int NS = K / BKg;   // 64

    // prologue: stage 0
    {
        uint32_t asb = smem_u32(&As[0][0]);
        uint32_t bsb = smem_u32(&Bs[0][0]);
        cp_async16(asb + (lm0 * APAD + lk0) * 4, Ab + (size_t)lm0 * K + lk0);
        cp_async16(asb + (lm1 * APAD + lk1) * 4, Ab + (size_t)lm1 * K + lk1);
        cp_async16(bsb + (lm0 * APAD + lk0) * 4, Bb + (size_t)lm0 * K + lk0);
        cp_async16(bsb + (lm1 * APAD + lk1) * 4, Bb + (size_t)lm1 * K + lk1);
        CP_COMMIT();
    }

    for (int s = 0; s < NS; ++s) {
        if (s + 1 < NS) {
            int buf = (s + 1) & 1;
            int kb = (s + 1) * BKg;
            uint32_t asb = smem_u32(&As[buf][0]);
            uint32_t bsb = smem_u32(&Bs[buf][0]);
            cp_async16(asb + (lm0 * APAD + lk0) * 4, Ab + (size_t)lm0 * K + kb + lk0);
            cp_async16(asb + (lm1 * APAD + lk1) * 4, Ab + (size_t)lm1 * K + kb + lk1);
            cp_async16(bsb + (lm0 * APAD + lk0) * 4, Bb + (size_t)lm0 * K + kb + lk0);
            cp_async16(bsb + (lm1 * APAD + lk1) * 4, Bb + (size_t)lm1 * K + kb + lk1);
            CP_COMMIT();
            CP_WAIT(1);
        } else {
            CP_WAIT(0);
        }
        __syncthreads();

        const float* as = As[s & 1];
        const float* bs = Bs[s & 1];
#pragma unroll
        for (int kk = 0; kk < BKg; kk += 8) {
            uint32_t afr[2][4];
#pragma unroll
            for (int i = 0; i < 2; i++) {
                int m = wm0 + 16 * i + gid;
                afr[i][0] = __float_as_uint(as[m * APAD + kk + tig]);
                afr[i][1] = __float_as_uint(as[(m + 8) * APAD + kk + tig]);
                afr[i][2] = __float_as_uint(as[m * APAD + kk + tig + 4]);
                afr[i][3] = __float_as_uint(as[(m + 8) * APAD + kk + tig + 4]);
            }
            uint32_t bfr[8][2];
#pragma unroll
            for (int j = 0; j < 8; j++) {
                int n = wn0 + 8 * j + gid;
                bfr[j][0] = __float_as_uint(bs[n * APAD + kk + tig]);
                bfr[j][1] = __float_as_uint(bs[n * APAD + kk + tig + 4]);
            }
#pragma unroll
            for (int i = 0; i < 2; i++)
#pragma unroll
                for (int j = 0; j < 8; j++)
                    mma_tf32(acc[i][j], afr[i], bfr[j]);
        }
        __syncthreads();
    }

    // epilogue: c0/c1 -> row, c2/c3 -> row+8; cols 2*tig, 2*tig+1
#pragma unroll
    for (int i = 0; i < 2; i++) {
        int row = m0 + wm0 + 16 * i + gid;
#pragma unroll
        for (int j = 0; j < 8; j++) {
            int col = n0 + wn0 + 8 * j + 2 * tig;
            float2 bv = *(const float2*)&bias[col];
            float2 o0, o1;
            o0.x = acc[i][j][0] + bv.x; o0.y = acc[i][j][1] + bv.y;
            o1.x = acc[i][j][2] + bv.x; o1.y = acc[i][j][3] + bv.y;
            *(float2*)&C[(size_t)row * N + col]       = o0;
            *(float2*)&C[(size_t)(row + 8) * N + col] = o1;
        }
    }
}

// ---------------- flash attention with the 1e-9 mask quirk (proven in R2) ----------
#define BQ 64
#define BK 64
#define KT_LD 66

__global__ __launch_bounds__(256)
void attention_kernel(const float* __restrict__ qkv,
                      const void* __restrict__ mask,
                      float* __restrict__ ctx) {
    extern __shared__ float sm[];
    float* Qs = sm;
    float* KT = Qs + BQ * Dh;
    float* Vs = KT + Dh * KT_LD;
    float* Ps = Vs + BK * Dh;
    unsigned char* Ms = (unsigned char*)(Ps + BQ * BK);

    const int qt = blockIdx.x;
    const int bh = blockIdx.y;
    const int b = bh / Hh, h = bh % Hh;
    const int tid = threadIdx.x;
    const int lane = tid & 31, warp = tid >> 5;
    const int q0 = qt * BQ;
    const int hoff = h * Dh;

    const int mode = g_mask_mode;
    const unsigned char*  m8  = (const unsigned char*)mask;
    const int*            m32 = (const int*)mask;
    const float*          mf  = (const float*)mask;
    const unsigned short* m16 = (const unsigned short*)mask;

    for (int i = tid; i < BQ * 16; i += 256) {
        int r = i >> 4, c = (i & 15) << 2;
        float4 v = *(const float4*)&qkv[((size_t)(b * Sq + q0 + r)) * E3 + hoff + c];
        *(float4*)&Qs[r * Dh + c] = v;
    }

    float mrow[8], lrow[8], acc0[8], acc1[8];
#pragma unroll
    for (int q = 0; q < 8; q++) { mrow[q] = -INFINITY; lrow[q] = 0.f; acc0[q] = 0.f; acc1[q] = 0.f; }
    const int qbase = warp * 8;

    for (int kt = 0; kt < Sq / BK; kt++) {
        const int k0 = kt * BK;
        __syncthreads();
        for (int i = tid; i < BK * 16; i += 256) {
            int r = i >> 4, c = (i & 15) << 2;
            const size_t row = (size_t)(b * Sq + k0 + r) * E3;
            float4 kv = *(const float4*)&qkv[row + Ed + hoff + c];
            KT[(c + 0) * KT_LD + r] = kv.x;
            KT[(c + 1) * KT_LD + r] = kv.y;
            KT[(c + 2) * KT_LD + r] = kv.z;
            KT[(c + 3) * KT_LD + r] = kv.w;
            float4 vv = *(const float4*)&qkv[row + 2 * Ed + hoff + c];
            *(float4*)&Vs[r * Dh + c] = vv;
        }
        for (int i = tid; i < (BQ * BK) / 4; i += 256) {
            int e = i << 2;
            int r = e >> 6, c = e & 63;
            size_t base = ((size_t)(b * Sq) + q0 + r) * Sq + k0 + c;
            uchar4 u;
            if (mode == 0) {
                u.x = m8[base] != 0; u.y = m8[base + 1] != 0;
                u.z = m8[base + 2] != 0; u.w = m8[base + 3] != 0;
            } else if (mode == 1) {
                u.x = m32[base] != 0; u.y = m32[base + 1] != 0;
                u.z = m32[base + 2] != 0; u.w = m32[base + 3] != 0;
            } else if (mode == 2) {
                u.x = mf[base] != 0.f; u.y = mf[base + 1] != 0.f;
                u.z = mf[base + 2] != 0.f; u.w = mf[base + 3] != 0.f;
            } else {
                u.x = m16[base] != 0; u.y = m16[base + 1] != 0;
                u.z = m16[base + 2] != 0; u.w = m16[base + 3] != 0;
            }
            *(uchar4*)&Ms[r * 64 + c] = u;
        }
        __syncthreads();

        float s0[8], s1[8];
#pragma unroll
        for (int q = 0; q < 8; q++) { s0[q] = 0.f; s1[q] = 0.f; }
#pragma unroll 4
        for (int d = 0; d < Dh; d++) {
            float2 kv = *(const float2*)&KT[d * KT_LD + 2 * lane];
#pragma unroll
            for (int q = 0; q < 8; q++) {
                float a = Qs[(qbase + q) * Dh + d];
                s0[q] += a * kv.x;
                s1[q] += a * kv.y;
            }
        }
#pragma unroll
        for (int q = 0; q < 8; q++) {
            unsigned char mA = Ms[(qbase + q) * 64 + 2 * lane];
            unsigned char mB = Ms[(qbase + q) * 64 + 2 * lane + 1];
            s0[q] = mA ? 1e-9f : s0[q] * 0.125f;
            s1[q] = mB ? 1e-9f : s1[q] * 0.125f;
        }
#pragma unroll
        for (int q = 0; q < 8; q++) {
            float mx = fmaxf(s0[q], s1[q]);
#pragma unroll
            for (int o = 16; o > 0; o >>= 1)
                mx = fmaxf(mx, __shfl_xor_sync(0xffffffffu, mx, o));
            float mnew = fmaxf(mrow[q], mx);
            float corr = __expf(mrow[q] - mnew);
            float p0 = __expf(s0[q] - mnew);
            float p1 = __expf(s1[q] - mnew);
            float ssum = p0 + p1;
#pragma unroll
            for (int o = 16; o > 0; o >>= 1)
                ssum += __shfl_xor_sync(0xffffffffu, ssum, o);
            lrow[q] = lrow[q] * corr + ssum;
            acc0[q] *= corr;
            acc1[q] *= corr;
            mrow[q] = mnew;
            float2 pw; pw.x = p0; pw.y = p1;
            *(float2*)&Ps[(qbase + q) * 64 + 2 * lane] = pw;
        }
        __syncwarp();
#pragma unroll 4
        for (int k = 0; k < BK; k++) {
            float v0 = Vs[k * Dh + lane];
            float v1 = Vs[k * Dh + lane + 32];
#pragma unroll
            for (int q = 0; q < 8; q++) {
                float p = Ps[(qbase + q) * 64 + k];
                acc0[q] += p * v0;
                acc1[q] += p * v1;
            }
        }
    }

    // epilogue: normalize, round to tf32 (feeds the tf32 output GEMM), write ctx
#pragma unroll
    for (int q = 0; q < 8; q++) {
        float inv = 1.f / lrow[q];
        int qg = q0 + qbase + q;
        size_t o = ((size_t)(b * Sq) + qg) * Ed + hoff;
        ctx[o + lane]      = to_tf32(acc0[q] * inv);
        ctx[o + lane + 32] = to_tf32(acc1[q] * inv);
    }
}

// ---------------- launcher ----------------
extern "C" void kernel_launch(void* const* d_in, const int* in_sizes, int n_in,
                              void* d_out, int out_size) {
    const float* x        = (const float*)d_in[0];
    const void*  amask    = d_in[1];
    const float* w_kernel = (const float*)d_in[2];
    const float* w_bias   = (const float*)d_in[3];
    const float* fc_kernel= (const float*)d_in[4];
    const float* fc_bias  = (const float*)d_in[5];
    float* out = (float*)d_out;

    float *qkv, *ctx, *xr, *bt, *bt2;
    cudaGetSymbolAddress((void**)&qkv, g_qkv);
    cudaGetSymbolAddress((void**)&ctx, g_ctx);
    cudaGetSymbolAddress((void**)&xr,  g_xr);
    cudaGetSymbolAddress((void**)&bt,  g_bt);
    cudaGetSymbolAddress((void**)&bt2, g_bt2);

    // 1. mask dtype detection
    long long nscan = in_sizes[1];
    if (nscan > (1 << 20)) nscan = (1 << 20);
    detect_mask_mode_kernel<<<1, 256>>>((const unsigned char*)amask, nscan);

    // 2. tf32 pre-rounding: x copy + transposed rounded weights
    {
        int n4 = (Mrows * Ed) / 4;
        round_copy_kernel<<<(n4 + 255) / 256, 256>>>((const float4*)x, (float4*)xr, n4);
        transpose_round_kernel<<<dim3(E3 / 32, Ed / 32), dim3(32, 8)>>>(w_kernel, bt, Ed, E3);
        transpose_round_kernel<<<dim3(Ed / 32, Ed / 32), dim3(32, 8)>>>(fc_kernel, bt2, Ed, Ed);
    }

    // 3. QKV projection (mma.sync tf32): qkv = xr * bt^T + w_bias
    {
        dim3 grid(E3 / 128, Mrows / 128);
        tf32_mma_gemm<<<grid, 256>>>(xr, bt, w_bias, qkv, E3, Ed);
    }

    // 4. flash attention (fp32, writes tf32-rounded ctx)
    {
        int smem = (BQ * Dh + Dh * KT_LD + BK * Dh + BQ * BK) * (int)sizeof(float)
                   + BQ * BK;
        cudaFuncSetAttribute(attention_kernel,
                             cudaFuncAttributeMaxDynamicSharedMemorySize, smem);
        dim3 grid(Sq / BQ, Bz * Hh);
        attention_kernel<<<grid, 256, smem>>>(qkv, amask, ctx);
    }

    // 5. output projection (mma.sync tf32): out = ctx * bt2^T + fc_bias
    {
        dim3 grid(Ed / 128, Mrows / 128);
        tf32_mma_gemm<<<grid, 256>>>(ctx, bt2, fc_bias, out, Ed, Ed);
    }
}

// round 5
// speedup vs baseline: 1.3910x; 1.0615x over previous
#include <cuda_runtime.h>
#include <cstdint>
#include <math.h>

// Problem constants
#define Bz 2
#define Sq 2048
#define Ed 1024
#define Hh 16
#define Dh 64
#define E3 3072
#define Mrows (Bz*Sq)   // 4096

// ---------------- device scratch ----------------
__device__ __align__(16) float g_qkv[Bz * Sq * E3];     // (B*S, 3E)
__device__ __align__(16) float g_ctx[Bz * Sq * Ed];     // (B*S, E), tf32-rounded
__device__ __align__(16) float g_xr [Bz * Sq * Ed];     // tf32-rounded x
__device__ __align__(16) float g_bt [E3 * Ed];          // w_kernel^T rounded
__device__ __align__(16) float g_bt2[Ed * Ed];          // fc_kernel^T rounded
__device__ int   g_mask_mode;

// ---------------- base-PTX helpers (NO 'a'-target features!) ----------------
__device__ __forceinline__ uint32_t smem_u32(const void* p) {
    uint32_t a;
    asm("{ .reg .u64 t; cvta.to.shared.u64 t, %1; cvt.u32.u64 %0, t; }" : "=r"(a) : "l"(p));
    return a;
}
__device__ __forceinline__ float to_tf32(float x) {
    float r; asm("cvt.rna.tf32.f32 %0, %1;" : "=f"(r) : "f"(x)); return r;
}
__device__ __forceinline__ void cp_async16(uint32_t dst, const void* src) {
    asm volatile("cp.async.cg.shared.global [%0], [%1], 16;" :: "r"(dst), "l"(src));
}
#define CP_COMMIT() asm volatile("cp.async.commit_group;" ::: "memory")
#define CP_WAIT(n)  asm volatile("cp.async.wait_group %0;" :: "n"(n) : "memory")

// D(16x8,f32) += A(16x8,tf32,row) * B(8x8,tf32,col)
__device__ __forceinline__ void mma_tf32(float* d, const uint32_t* a, const uint32_t* b) {
    asm volatile("mma.sync.aligned.m16n8k8.row.col.f32.tf32.tf32.f32 "
                 "{%0,%1,%2,%3}, {%4,%5,%6,%7}, {%8,%9}, {%0,%1,%2,%3};"
                 : "+f"(d[0]), "+f"(d[1]), "+f"(d[2]), "+f"(d[3])
                 : "r"(a[0]), "r"(a[1]), "r"(a[2]), "r"(a[3]),
                   "r"(b[0]), "r"(b[1]));
}

// ---------------- mask dtype detector (proven) ----------------
__global__ void detect_mask_mode_kernel(const unsigned char* __restrict__ m, long long nbytes) {
    __shared__ int cnt[5];
    if (threadIdx.x < 5) cnt[threadIdx.x] = 0;
    __syncthreads();
    int local[5] = {0, 0, 0, 0, 0};
    for (long long i = threadIdx.x; i < nbytes; i += blockDim.x) {
        unsigned char v = m[i];
        if (v) { local[(int)(i & 3)]++; if (v != 1) local[4]++; }
    }
#pragma unroll
    for (int j = 0; j < 5; j++) if (local[j]) atomicAdd(&cnt[j], local[j]);
    __syncthreads();
    if (threadIdx.x == 0) {
        int c0 = cnt[0], c1 = cnt[1], weird = cnt[4];
        int mode;
        if (c1 == 0 && cnt[2] == 0 && cnt[3] == 0) mode = 1;
        else if (c0 == 0 && c1 == 0)               mode = 2;
        else if (weird > 0)                        mode = 3;
        else                                       mode = 0;
        g_mask_mode = mode;
    }
}

// ---------------- tf32 pre-rounding utilities ----------------
__global__ void round_copy_kernel(const float4* __restrict__ in, float4* __restrict__ out, int n4) {
    int i = blockIdx.x * blockDim.x + threadIdx.x;
    if (i < n4) {
        float4 v = in[i];
        v.x = to_tf32(v.x); v.y = to_tf32(v.y); v.z = to_tf32(v.z); v.w = to_tf32(v.w);
        out[i] = v;
    }
}
__global__ void transpose_round_kernel(const float* __restrict__ in, float* __restrict__ out,
                                       int K, int N) {
    __shared__ float t[32][33];
    int n0 = blockIdx.x * 32, k0 = blockIdx.y * 32;
    for (int i = threadIdx.y; i < 32; i += 8)
        t[i][threadIdx.x] = to_tf32(in[(size_t)(k0 + i) * N + n0 + threadIdx.x]);
    __syncthreads();
    for (int i = threadIdx.y; i < 32; i += 8)
        out[(size_t)(n0 + i) * K + k0 + threadIdx.x] = t[threadIdx.x][i];
}

// ---------------- tf32 mma.sync GEMM (proven in R4) ----------------
#define APAD 20
#define BKg 16

__global__ __launch_bounds__(256, 1)
void tf32_mma_gemm(const float* __restrict__ A, const float* __restrict__ Bt,
                   const float* __restrict__ bias, float* __restrict__ C,
                   int N, int K)
{
    __shared__ float As[2][128 * APAD];
    __shared__ float Bs[2][128 * APAD];

    const int tid = threadIdx.x;
    const int warp = tid >> 5, lane = tid & 31;
    const int gid = lane >> 2;
    const int tig = lane & 3;
    const int m0 = blockIdx.y * 128, n0 = blockIdx.x * 128;
    const int wm0 = (warp & 3) * 32;
    const int wn0 = (warp >> 2) * 64;

    const float* Ab = A + (size_t)m0 * K;
    const float* Bb = Bt + (size_t)n0 * K;

    float acc[2][8][4];
#pragma unroll
    for (int i = 0; i < 2; i++)
#pragma unroll
        for (int j = 0; j < 8; j++)
#pragma unroll
            for (int r = 0; r < 4; r++) acc[i][j][r] = 0.f;

    const int c0g = tid, c1g = 256 + tid;
    const int lm0 = c0g >> 2, lk0 = (c0g & 3) << 2;
    const int lm1 = c1g >> 2, lk1 = (c1g & 3) << 2;

    const int NS = K / BKg;

    {
        uint32_t asb = smem_u32(&As[0][0]);
        uint32_t bsb = smem_u32(&Bs[0][0]);
        cp_async16(asb + (lm0 * APAD + lk0) * 4, Ab + (size_t)lm0 * K + lk0);
        cp_async16(asb + (lm1 * APAD + lk1) * 4, Ab + (size_t)lm1 * K + lk1);
        cp_async16(bsb + (lm0 * APAD + lk0) * 4, Bb + (size_t)lm0 * K + lk0);
        cp_async16(bsb + (lm1 * APAD + lk1) * 4, Bb + (size_t)lm1 * K + lk1);
        CP_COMMIT();
    }

    for (int s = 0; s < NS; ++s) {
        if (s + 1 < NS) {
            int buf = (s + 1) & 1;
            int kb = (s + 1) * BKg;
            uint32_t asb = smem_u32(&As[buf][0]);
            uint32_t bsb = smem_u32(&Bs[buf][0]);
            cp_async16(asb + (lm0 * APAD + lk0) * 4, Ab + (size_t)lm0 * K + kb + lk0);
            cp_async16(asb + (lm1 * APAD + lk1) * 4, Ab + (size_t)lm1 * K + kb + lk1);
            cp_async16(bsb + (lm0 * APAD + lk0) * 4, Bb + (size_t)lm0 * K + kb + lk0);
            cp_async16(bsb + (lm1 * APAD + lk1) * 4, Bb + (size_t)lm1 * K + kb + lk1);
            CP_COMMIT();
            CP_WAIT(1);
        } else {
            CP_WAIT(0);
        }
        __syncthreads();

        const float* as = As[s & 1];
        const float* bs = Bs[s & 1];
#pragma unroll
        for (int kk = 0; kk < BKg; kk += 8) {
            uint32_t afr[2][4];
#pragma unroll
            for (int i = 0; i < 2; i++) {
                int m = wm0 + 16 * i + gid;
                afr[i][0] = __float_as_uint(as[m * APAD + kk + tig]);
                afr[i][1] = __float_as_uint(as[(m + 8) * APAD + kk + tig]);
                afr[i][2] = __float_as_uint(as[m * APAD + kk + tig + 4]);
                afr[i][3] = __float_as_uint(as[(m + 8) * APAD + kk + tig + 4]);
            }
            uint32_t bfr[8][2];
#pragma unroll
            for (int j = 0; j < 8; j++) {
                int n = wn0 + 8 * j + gid;
                bfr[j][0] = __float_as_uint(bs[n * APAD + kk + tig]);
                bfr[j][1] = __float_as_uint(bs[n * APAD + kk + tig + 4]);
            }
#pragma unroll
            for (int i = 0; i < 2; i++)
#pragma unroll
                for (int j = 0; j < 8; j++)
                    mma_tf32(acc[i][j], afr[i], bfr[j]);
        }
        __syncthreads();
    }

#pragma unroll
    for (int i = 0; i < 2; i++) {
        int row = m0 + wm0 + 16 * i + gid;
#pragma unroll
        for (int j = 0; j < 8; j++) {
            int col = n0 + wn0 + 8 * j + 2 * tig;
            float2 bv = *(const float2*)&bias[col];
            float2 o0, o1;
            o0.x = acc[i][j][0] + bv.x; o0.y = acc[i][j][1] + bv.y;
            o1.x = acc[i][j][2] + bv.x; o1.y = acc[i][j][3] + bv.y;
            *(float2*)&C[(size_t)row * N + col]       = o0;
            *(float2*)&C[(size_t)(row + 8) * N + col] = o1;
        }
    }
}

// ---------------- tensor-core flash attention (3xTF32 QK^T, tf32 PV) -------------
// Grid (Sq/128, B*H), 256 threads = 8 warps, warp owns 16 q rows.
// K tile [64][68] raw fp32 (hi/lo split at fragment load); V tile [64][68]
// tf32-rounded, read transposed (conflict-free with pad 68); P per-warp rows in Ps.
#define AT_PAD 68
#define KS_OFF 0
#define VS_OFF (64 * AT_PAD)
#define PS_OFF (2 * 64 * AT_PAD)
#define MS_OFF (2 * 64 * AT_PAD + 128 * AT_PAD)   // float offset of mask bytes
#define AT_SMEM ((2 * 64 * AT_PAD + 128 * AT_PAD) * 4 + 128 * 64)

__global__ __launch_bounds__(256, 1)
void attention_mma_kernel(const float* __restrict__ qkv,
                          const void* __restrict__ mask,
                          float* __restrict__ ctx) {
    extern __shared__ float sm[];
    float* Ks = sm + KS_OFF;
    float* Vs = sm + VS_OFF;
    float* Ps = sm + PS_OFF;
    unsigned char* Ms = (unsigned char*)(sm + MS_OFF);

    const int qt = blockIdx.x, bh = blockIdx.y;
    const int b = bh >> 4, h = bh & 15;
    const int tid = threadIdx.x, lane = tid & 31, warp = tid >> 5;
    const int gid = lane >> 2, tig = lane & 3;
    const int q0 = qt * 128, hoff = h * Dh;
    const int wrow = warp * 16;
    const int r0 = wrow + gid, r1 = r0 + 8;

    const int mode = g_mask_mode;
    const unsigned char*  m8  = (const unsigned char*)mask;
    const int*            m32 = (const int*)mask;
    const float*          mf  = (const float*)mask;
    const unsigned short* m16 = (const unsigned short*)mask;

    // stage Q tile into Ps (reused later for P)
#pragma unroll
    for (int t = 0; t < 8; t++) {
        int idx = tid + t * 256;
        int r = idx >> 4, c = (idx & 15) << 2;
        float4 v = *(const float4*)&qkv[(size_t)(b * Sq + q0 + r) * E3 + hoff + c];
        *(float4*)&Ps[r * AT_PAD + c] = v;
    }
    __syncthreads();

    // Q fragments, hi/lo split (register-resident for all 32 k-tiles)
    uint32_t qh[8][4], ql[8][4];
#pragma unroll
    for (int kk = 0; kk < 8; kk++) {
        float v0 = Ps[r0 * AT_PAD + 8 * kk + tig];
        float v1 = Ps[r1 * AT_PAD + 8 * kk + tig];
        float v2 = Ps[r0 * AT_PAD + 8 * kk + tig + 4];
        float v3 = Ps[r1 * AT_PAD + 8 * kk + tig + 4];
        float h0 = to_tf32(v0), h1 = to_tf32(v1), h2 = to_tf32(v2), h3 = to_tf32(v3);
        qh[kk][0] = __float_as_uint(h0); ql[kk][0] = __float_as_uint(to_tf32(v0 - h0));
        qh[kk][1] = __float_as_uint(h1); ql[kk][1] = __float_as_uint(to_tf32(v1 - h1));
        qh[kk][2] = __float_as_uint(h2); ql[kk][2] = __float_as_uint(to_tf32(v2 - h2));
        qh[kk][3] = __float_as_uint(h3); ql[kk][3] = __float_as_uint(to_tf32(v3 - h3));
    }

    float mrow0 = -INFINITY, mrow1 = -INFINITY, lrow0 = 0.f, lrow1 = 0.f;
    float oacc[8][4];
#pragma unroll
    for (int j = 0; j < 8; j++)
#pragma unroll
        for (int r = 0; r < 4; r++) oacc[j][r] = 0.f;

    for (int kt = 0; kt < Sq / 64; kt++) {
        const int k0 = kt * 64;
        __syncthreads();   // previous tile fully consumed
        // load K (raw) and V (tf32-rounded), 64x64 each
#pragma unroll
        for (int t = 0; t < 4; t++) {
            int idx = tid + t * 256;
            int r = idx >> 4, c = (idx & 15) << 2;
            size_t row = (size_t)(b * Sq + k0 + r) * E3 + hoff;
            float4 kv = *(const float4*)&qkv[row + Ed + c];
            *(float4*)&Ks[r * AT_PAD + c] = kv;
            float4 vv = *(const float4*)&qkv[row + 2 * Ed + c];
            vv.x = to_tf32(vv.x); vv.y = to_tf32(vv.y);
            vv.z = to_tf32(vv.z); vv.w = to_tf32(vv.w);
            *(float4*)&Vs[r * AT_PAD + c] = vv;
        }
        // mask tile 128x64 bytes
#pragma unroll
        for (int t = 0; t < 8; t++) {
            int e = (tid + t * 256) << 2;
            int r = e >> 6, c = e & 63;
            size_t base = ((size_t)(b * Sq) + q0 + r) * Sq + k0 + c;
            uchar4 u;
            if (mode == 0) {
                u.x = m8[base] != 0; u.y = m8[base + 1] != 0;
                u.z = m8[base + 2] != 0; u.w = m8[base + 3] != 0;
            } else if (mode == 1) {
                u.x = m32[base] != 0; u.y = m32[base + 1] != 0;
                u.z = m32[base + 2] != 0; u.w = m32[base + 3] != 0;
            } else if (mode == 2) {
                u.x = mf[base] != 0.f; u.y = mf[base + 1] != 0.f;
                u.z = mf[base + 2] != 0.f; u.w = mf[base + 3] != 0.f;
            } else {
                u.x = m16[base] != 0; u.y = m16[base + 1] != 0;
                u.z = m16[base + 2] != 0; u.w = m16[base + 3] != 0;
            }
            *(uchar4*)&Ms[r * 64 + c] = u;
        }
        __syncthreads();

        // QK^T with 3xTF32 (fp32-grade scores)
        float sc[8][4];
#pragma unroll
        for (int j = 0; j < 8; j++)
#pragma unroll
            for (int r = 0; r < 4; r++) sc[j][r] = 0.f;
#pragma unroll
        for (int kk = 0; kk < 8; kk++) {
#pragma unroll
            for (int j = 0; j < 8; j++) {
                const float* kp = &Ks[(8 * j + gid) * AT_PAD + 8 * kk + tig];
                float b0 = kp[0], b1 = kp[4];
                float h0 = to_tf32(b0), h1 = to_tf32(b1);
                uint32_t bhh[2] = { __float_as_uint(h0), __float_as_uint(h1) };
                uint32_t bll[2] = { __float_as_uint(to_tf32(b0 - h0)),
                                    __float_as_uint(to_tf32(b1 - h1)) };
                mma_tf32(sc[j], qh[kk], bhh);
                mma_tf32(sc[j], ql[kk], bhh);
                mma_tf32(sc[j], qh[kk], bll);
            }
        }

        // scale + mask quirk (masked -> literally 1e-9)
#pragma unroll
        for (int j = 0; j < 8; j++) {
            int col = 8 * j + 2 * tig;
            unsigned char m00 = Ms[r0 * 64 + col], m01 = Ms[r0 * 64 + col + 1];
            unsigned char m10 = Ms[r1 * 64 + col], m11 = Ms[r1 * 64 + col + 1];
            sc[j][0] = m00 ? 1e-9f : sc[j][0] * 0.125f;
            sc[j][1] = m01 ? 1e-9f : sc[j][1] * 0.125f;
            sc[j][2] = m10 ? 1e-9f : sc[j][2] * 0.125f;
            sc[j][3] = m11 ? 1e-9f : sc[j][3] * 0.125f;
        }

        // online softmax (two rows per thread; row group = quad lanes)
        float mx0 = -INFINITY, mx1 = -INFINITY;
#pragma unroll
        for (int j = 0; j < 8; j++) {
            mx0 = fmaxf(mx0, fmaxf(sc[j][0], sc[j][1]));
            mx1 = fmaxf(mx1, fmaxf(sc[j][2], sc[j][3]));
        }
        mx0 = fmaxf(mx0, __shfl_xor_sync(0xffffffffu, mx0, 1));
        mx0 = fmaxf(mx0, __shfl_xor_sync(0xffffffffu, mx0, 2));
        mx1 = fmaxf(mx1, __shfl_xor_sync(0xffffffffu, mx1, 1));
        mx1 = fmaxf(mx1, __shfl_xor_sync(0xffffffffu, mx1, 2));
        float mn0 = fmaxf(mrow0, mx0), mn1 = fmaxf(mrow1, mx1);
        float corr0 = __expf(mrow0 - mn0), corr1 = __expf(mrow1 - mn1);
        float sum0 = 0.f, sum1 = 0.f;
#pragma unroll
        for (int j = 0; j < 8; j++) {
            sc[j][0] = __expf(sc[j][0] - mn0);
            sc[j][1] = __expf(sc[j][1] - mn0);
            sc[j][2] = __expf(sc[j][2] - mn1);
            sc[j][3] = __expf(sc[j][3] - mn1);
            sum0 += sc[j][0] + sc[j][1];
            sum1 += sc[j][2] + sc[j][3];
        }
        sum0 += __shfl_xor_sync(0xffffffffu, sum0, 1);
        sum0 += __shfl_xor_sync(0xffffffffu, sum0, 2);
        sum1 += __shfl_xor_sync(0xffffffffu, sum1, 1);
        sum1 += __shfl_xor_sync(0xffffffffu, sum1, 2);
        lrow0 = lrow0 * corr0 + sum0;
        lrow1 = lrow1 * corr1 + sum1;
        mrow0 = mn0; mrow1 = mn1;
#pragma unroll
        for (int j = 0; j < 8; j++) {
            oacc[j][0] *= corr0; oacc[j][1] *= corr0;
            oacc[j][2] *= corr1; oacc[j][3] *= corr1;
        }
        // write P (tf32-rounded) to per-warp rows of Ps
#pragma unroll
        for (int j = 0; j < 8; j++) {
            int col = 8 * j + 2 * tig;
            float2 p0, p1;
            p0.x = to_tf32(sc[j][0]); p0.y = to_tf32(sc[j][1]);
            p1.x = to_tf32(sc[j][2]); p1.y = to_tf32(sc[j][3]);
            *(float2*)&Ps[r0 * AT_PAD + col] = p0;
            *(float2*)&Ps[r1 * AT_PAD + col] = p1;
        }
        __syncwarp();

        // PV: out += P(16x64) * V(64x64); V read transposed from row-major tile
#pragma unroll
        for (int kk = 0; kk < 8; kk++) {
            uint32_t a[4];
            a[0] = __float_as_uint(Ps[r0 * AT_PAD + 8 * kk + tig]);
            a[1] = __float_as_uint(Ps[r1 * AT_PAD + 8 * kk + tig]);
            a[2] = __float_as_uint(Ps[r0 * AT_PAD + 8 * kk + tig + 4]);
            a[3] = __float_as_uint(Ps[r1 * AT_PAD + 8 * kk + tig + 4]);
#pragma unroll
            for (int j = 0; j < 8; j++) {
                uint32_t bb[2] = {
                    __float_as_uint(Vs[(8 * kk + tig) * AT_PAD + 8 * j + gid]),
                    __float_as_uint(Vs[(8 * kk + tig + 4) * AT_PAD + 8 * j + gid])
                };
                mma_tf32(oacc[j], a, bb);
            }
        }
    }

    // epilogue: normalize, tf32-round (feeds output GEMM), write ctx
    float inv0 = 1.f / lrow0, inv1 = 1.f / lrow1;
    const size_t row0 = (size_t)(b * Sq + q0 + wrow + gid);
#pragma unroll
    for (int j = 0; j < 8; j++) {
        int col = hoff + 8 * j + 2 * tig;
        float2 o0, o1;
        o0.x = to_tf32(oacc[j][0] * inv0); o0.y = to_tf32(oacc[j][1] * inv0);
        o1.x = to_tf32(oacc[j][2] * inv1); o1.y = to_tf32(oacc[j][3] * inv1);
        *(float2*)&ctx[row0 * Ed + col]       = o0;
        *(float2*)&ctx[(row0 + 8) * Ed + col] = o1;
    }
}

// ---------------- launcher ----------------
extern "C" void kernel_launch(void* const* d_in, const int* in_sizes, int n_in,
                              void* d_out, int out_size) {
    const float* x        = (const float*)d_in[0];
    const void*  amask    = d_in[1];
    const float* w_kernel = (const float*)d_in[2];
    const float* w_bias   = (const float*)d_in[3];
    const float* fc_kernel= (const float*)d_in[4];
    const float* fc_bias  = (const float*)d_in[5];
    float* out = (float*)d_out;

    float *qkv, *ctx, *xr, *bt, *bt2;
    cudaGetSymbolAddress((void**)&qkv, g_qkv);
    cudaGetSymbolAddress((void**)&ctx, g_ctx);
    cudaGetSymbolAddress((void**)&xr,  g_xr);
    cudaGetSymbolAddress((void**)&bt,  g_bt);
    cudaGetSymbolAddress((void**)&bt2, g_bt2);

    // 1. mask dtype detection
    long long nscan = in_sizes[1];
    if (nscan > (1 << 20)) nscan = (1 << 20);
    detect_mask_mode_kernel<<<1, 256>>>((const unsigned char*)amask, nscan);

    // 2. tf32 pre-rounding
    {
        int n4 = (Mrows * Ed) / 4;
        round_copy_kernel<<<(n4 + 255) / 256, 256>>>((const float4*)x, (float4*)xr, n4);
        transpose_round_kernel<<<dim3(E3 / 32, Ed / 32), dim3(32, 8)>>>(w_kernel, bt, Ed, E3);
        transpose_round_kernel<<<dim3(Ed / 32, Ed / 32), dim3(32, 8)>>>(fc_kernel, bt2, Ed, Ed);
    }

    // 3. QKV projection (mma.sync tf32)
    {
        dim3 grid(E3 / 128, Mrows / 128);
        tf32_mma_gemm<<<grid, 256>>>(xr, bt, w_bias, qkv, E3, Ed);
    }

    // 4. tensor-core flash attention
    {
        cudaFuncSetAttribute(attention_mma_kernel,
                             cudaFuncAttributeMaxDynamicSharedMemorySize, AT_SMEM);
        dim3 grid(Sq / 128, Bz * Hh);
        attention_mma_kernel<<<grid, 256, AT_SMEM>>>(qkv, amask, ctx);
    }

    // 5. output projection (mma.sync tf32)
    {
        dim3 grid(Ed / 128, Mrows / 128);
        tf32_mma_gemm<<<grid, 256>>>(ctx, bt2, fc_bias, out, Ed, Ed);
    }
}

// round 6
// speedup vs baseline: 1.6548x; 1.1897x over previous
#include <cuda_runtime.h>
#include <cstdint>
#include <math.h>

// Problem constants
#define Bz 2
#define Sq 2048
#define Ed 1024
#define Hh 16
#define Dh 64
#define E3 3072
#define Mrows (Bz*Sq)   // 4096

// ---------------- device scratch ----------------
__device__ __align__(16) float g_qkv[Bz * Sq * E3];     // (B*S, 3E)
__device__ __align__(16) float g_ctx[Bz * Sq * Ed];     // (B*S, E), tf32-rounded
__device__ __align__(16) float g_xr [Bz * Sq * Ed];     // tf32-rounded x
__device__ __align__(16) float g_bt [E3 * Ed];          // w_kernel^T rounded
__device__ __align__(16) float g_bt2[Ed * Ed];          // fc_kernel^T rounded
__device__ __align__(16) float g_kh [Bz * Sq * Ed];     // K hi (tf32)
__device__ __align__(16) float g_kl [Bz * Sq * Ed];     // K lo residual (tf32)
__device__ __align__(16) float g_vr [Bz * Sq * Ed];     // V rounded (tf32)
__device__ __align__(16) unsigned long long g_mbits[(size_t)Bz * Sq * Sq / 64]; // 1MB bitmask
__device__ int   g_mask_mode;

// ---------------- base-PTX helpers (NO 'a'-target features!) ----------------
__device__ __forceinline__ uint32_t smem_u32(const void* p) {
    uint32_t a;
    asm("{ .reg .u64 t; cvta.to.shared.u64 t, %1; cvt.u32.u64 %0, t; }" : "=r"(a) : "l"(p));
    return a;
}
__device__ __forceinline__ float to_tf32(float x) {
    float r; asm("cvt.rna.tf32.f32 %0, %1;" : "=f"(r) : "f"(x)); return r;
}
__device__ __forceinline__ void cp_async16(uint32_t dst, const void* src) {
    asm volatile("cp.async.cg.shared.global [%0], [%1], 16;" :: "r"(dst), "l"(src));
}
#define CP_COMMIT() asm volatile("cp.async.commit_group;" ::: "memory")
#define CP_WAIT(n)  asm volatile("cp.async.wait_group %0;" :: "n"(n) : "memory")

// D(16x8,f32) += A(16x8,tf32,row) * B(8x8,tf32,col)
__device__ __forceinline__ void mma_tf32(float* d, const uint32_t* a, const uint32_t* b) {
    asm volatile("mma.sync.aligned.m16n8k8.row.col.f32.tf32.tf32.f32 "
                 "{%0,%1,%2,%3}, {%4,%5,%6,%7}, {%8,%9}, {%0,%1,%2,%3};"
                 : "+f"(d[0]), "+f"(d[1]), "+f"(d[2]), "+f"(d[3])
                 : "r"(a[0]), "r"(a[1]), "r"(a[2]), "r"(a[3]),
                   "r"(b[0]), "r"(b[1]));
}

// ---------------- mask dtype detector (proven) ----------------
__global__ void detect_mask_mode_kernel(const unsigned char* __restrict__ m, long long nbytes) {
    __shared__ int cnt[5];
    if (threadIdx.x < 5) cnt[threadIdx.x] = 0;
    __syncthreads();
    int local[5] = {0, 0, 0, 0, 0};
    for (long long i = threadIdx.x; i < nbytes; i += blockDim.x) {
        unsigned char v = m[i];
        if (v) { local[(int)(i & 3)]++; if (v != 1) local[4]++; }
    }
#pragma unroll
    for (int j = 0; j < 5; j++) if (local[j]) atomicAdd(&cnt[j], local[j]);
    __syncthreads();
    if (threadIdx.x == 0) {
        int c0 = cnt[0], c1 = cnt[1], weird = cnt[4];
        int mode;
        if (c1 == 0 && cnt[2] == 0 && cnt[3] == 0) mode = 1;
        else if (c0 == 0 && c1 == 0)               mode = 2;
        else if (weird > 0)                        mode = 3;
        else                                       mode = 0;
        g_mask_mode = mode;
    }
}

// ---------------- mask bit-packing: 64 elements -> one uint64 ----------------
__global__ void pack_mask_kernel(const void* __restrict__ mask,
                                 unsigned long long* __restrict__ mbits) {
    int w = blockIdx.x * blockDim.x + threadIdx.x;   // 131072 words
    int mode = g_mask_mode;
    unsigned long long bits = 0;
    if (mode == 0) {
        const uint4* p = (const uint4*)((const unsigned char*)mask + (size_t)w * 64);
#pragma unroll
        for (int i = 0; i < 4; i++) {
            uint4 v = p[i];
            uint32_t ws[4] = {v.x, v.y, v.z, v.w};
#pragma unroll
            for (int j = 0; j < 4; j++)
#pragma unroll
                for (int bq = 0; bq < 4; bq++)
                    if ((ws[j] >> (8 * bq)) & 0xFFu)
                        bits |= 1ull << (i * 16 + j * 4 + bq);
        }
    } else if (mode == 1 || mode == 2) {
        const uint4* p = (const uint4*)((const uint32_t*)mask + (size_t)w * 64);
#pragma unroll
        for (int i = 0; i < 16; i++) {
            uint4 v = p[i];
            if (v.x) bits |= 1ull << (i * 4 + 0);
            if (v.y) bits |= 1ull << (i * 4 + 1);
            if (v.z) bits |= 1ull << (i * 4 + 2);
            if (v.w) bits |= 1ull << (i * 4 + 3);
        }
    } else {
        const uint4* p = (const uint4*)((const unsigned short*)mask + (size_t)w * 64);
#pragma unroll
        for (int i = 0; i < 8; i++) {
            uint4 v = p[i];
            uint32_t ws[4] = {v.x, v.y, v.z, v.w};
#pragma unroll
            for (int j = 0; j < 4; j++) {
                if (ws[j] & 0xFFFFu) bits |= 1ull << (i * 8 + j * 2);
                if (ws[j] >> 16)     bits |= 1ull << (i * 8 + j * 2 + 1);
            }
        }
    }
    mbits[w] = bits;
}

// ---------------- tf32 pre-rounding utilities ----------------
__global__ void round_copy_kernel(const float4* __restrict__ in, float4* __restrict__ out, int n4) {
    int i = blockIdx.x * blockDim.x + threadIdx.x;
    if (i < n4) {
        float4 v = in[i];
        v.x = to_tf32(v.x); v.y = to_tf32(v.y); v.z = to_tf32(v.z); v.w = to_tf32(v.w);
        out[i] = v;
    }
}
__global__ void transpose_round_kernel(const float* __restrict__ in, float* __restrict__ out,
                                       int K, int N) {
    __shared__ float t[32][33];
    int n0 = blockIdx.x * 32, k0 = blockIdx.y * 32;
    for (int i = threadIdx.y; i < 32; i += 8)
        t[i][threadIdx.x] = to_tf32(in[(size_t)(k0 + i) * N + n0 + threadIdx.x]);
    __syncthreads();
    for (int i = threadIdx.y; i < 32; i += 8)
        out[(size_t)(n0 + i) * K + k0 + threadIdx.x] = t[threadIdx.x][i];
}

// K -> (hi, lo) split; V -> rna-rounded. One pass over the qkv scratch.
__global__ void prep_kv_kernel(const float* __restrict__ qkv,
                               float* __restrict__ kh, float* __restrict__ kl,
                               float* __restrict__ vr) {
    int i = blockIdx.x * blockDim.x + threadIdx.x;
    if (i >= Mrows * (Ed / 4)) return;
    int row = i / (Ed / 4), c = (i % (Ed / 4)) * 4;
    float4 k = *(const float4*)&qkv[(size_t)row * E3 + Ed + c];
    float4 v = *(const float4*)&qkv[(size_t)row * E3 + 2 * Ed + c];
    float4 h, l;
    h.x = to_tf32(k.x); l.x = to_tf32(k.x - h.x);
    h.y = to_tf32(k.y); l.y = to_tf32(k.y - h.y);
    h.z = to_tf32(k.z); l.z = to_tf32(k.z - h.z);
    h.w = to_tf32(k.w); l.w = to_tf32(k.w - h.w);
    v.x = to_tf32(v.x); v.y = to_tf32(v.y); v.z = to_tf32(v.z); v.w = to_tf32(v.w);
    *(float4*)&kh[(size_t)row * Ed + c] = h;
    *(float4*)&kl[(size_t)row * Ed + c] = l;
    *(float4*)&vr[(size_t)row * Ed + c] = v;
}

// ---------------- tf32 mma.sync GEMM (proven in R4) ----------------
#define APAD 20
#define BKg 16

__global__ __launch_bounds__(256, 1)
void tf32_mma_gemm(const float* __restrict__ A, const float* __restrict__ Bt,
                   const float* __restrict__ bias, float* __restrict__ C,
                   int N, int K)
{
    __shared__ float As[2][128 * APAD];
    __shared__ float Bs[2][128 * APAD];

    const int tid = threadIdx.x;
    const int warp = tid >> 5, lane = tid & 31;
    const int gid = lane >> 2;
    const int tig = lane & 3;
    const int m0 = blockIdx.y * 128, n0 = blockIdx.x * 128;
    const int wm0 = (warp & 3) * 32;
    const int wn0 = (warp >> 2) * 64;

    const float* Ab = A + (size_t)m0 * K;
    const float* Bb = Bt + (size_t)n0 * K;

    float acc[2][8][4];
#pragma unroll
    for (int i = 0; i < 2; i++)
#pragma unroll
        for (int j = 0; j < 8; j++)
#pragma unroll
            for (int r = 0; r < 4; r++) acc[i][j][r] = 0.f;

    const int c0g = tid, c1g = 256 + tid;
    const int lm0 = c0g >> 2, lk0 = (c0g & 3) << 2;
    const int lm1 = c1g >> 2, lk1 = (c1g & 3) << 2;

    const int NS = K / BKg;

    {
        uint32_t asb = smem_u32(&As[0][0]);
        uint32_t bsb = smem_u32(&Bs[0][0]);
        cp_async16(asb + (lm0 * APAD + lk0) * 4, Ab + (size_t)lm0 * K + lk0);
        cp_async16(asb + (lm1 * APAD + lk1) * 4, Ab + (size_t)lm1 * K + lk1);
        cp_async16(bsb + (lm0 * APAD + lk0) * 4, Bb + (size_t)lm0 * K + lk0);
        cp_async16(bsb + (lm1 * APAD + lk1) * 4, Bb + (size_t)lm1 * K + lk1);
        CP_COMMIT();
    }

    for (int s = 0; s < NS; ++s) {
        if (s + 1 < NS) {
            int buf = (s + 1) & 1;
            int kb = (s + 1) * BKg;
            uint32_t asb = smem_u32(&As[buf][0]);
            uint32_t bsb = smem_u32(&Bs[buf][0]);
            cp_async16(asb + (lm0 * APAD + lk0) * 4, Ab + (size_t)lm0 * K + kb + lk0);
            cp_async16(asb + (lm1 * APAD + lk1) * 4, Ab + (size_t)lm1 * K + kb + lk1);
            cp_async16(bsb + (lm0 * APAD + lk0) * 4, Bb + (size_t)lm0 * K + kb + lk0);
            cp_async16(bsb + (lm1 * APAD + lk1) * 4, Bb + (size_t)lm1 * K + kb + lk1);
            CP_COMMIT();
            CP_WAIT(1);
        } else {
            CP_WAIT(0);
        }
        __syncthreads();

        const float* as = As[s & 1];
        const float* bs = Bs[s & 1];
#pragma unroll
        for (int kk = 0; kk < BKg; kk += 8) {
            uint32_t afr[2][4];
#pragma unroll
            for (int i = 0; i < 2; i++) {
                int m = wm0 + 16 * i + gid;
                afr[i][0] = __float_as_uint(as[m * APAD + kk + tig]);
                afr[i][1] = __float_as_uint(as[(m + 8) * APAD + kk + tig]);
                afr[i][2] = __float_as_uint(as[m * APAD + kk + tig + 4]);
                afr[i][3] = __float_as_uint(as[(m + 8) * APAD + kk + tig + 4]);
            }
            uint32_t bfr[8][2];
#pragma unroll
            for (int j = 0; j < 8; j++) {
                int n = wn0 + 8 * j + gid;
                bfr[j][0] = __float_as_uint(bs[n * APAD + kk + tig]);
                bfr[j][1] = __float_as_uint(bs[n * APAD + kk + tig + 4]);
            }
#pragma unroll
            for (int i = 0; i < 2; i++)
#pragma unroll
                for (int j = 0; j < 8; j++)
                    mma_tf32(acc[i][j], afr[i], bfr[j]);
        }
        __syncthreads();
    }

#pragma unroll
    for (int i = 0; i < 2; i++) {
        int row = m0 + wm0 + 16 * i + gid;
#pragma unroll
        for (int j = 0; j < 8; j++) {
            int col = n0 + wn0 + 8 * j + 2 * tig;
            float2 bv = *(const float2*)&bias[col];
            float2 o0, o1;
            o0.x = acc[i][j][0] + bv.x; o0.y = acc[i][j][1] + bv.y;
            o1.x = acc[i][j][2] + bv.x; o1.y = acc[i][j][3] + bv.y;
            *(float2*)&C[(size_t)row * N + col]       = o0;
            *(float2*)&C[(size_t)(row + 8) * N + col] = o1;
        }
    }
}

// ---------------- tensor-core flash attention v2 -------------------------
// Pre-split Kh/Kl, pre-rounded V, bitmask. cp.async double-buffered tiles.
// SMEM floats: KH[2][64*68] KL[2][64*68] VS[2][64*68] PS[128*68]
#define AP 68
#define SM_KH(buf) ((buf) * 4352)
#define SM_KL(buf) (8704 + (buf) * 4352)
#define SM_VS(buf) (17408 + (buf) * 4352)
#define SM_PS      26112
#define AT2_SMEM   ((26112 + 128 * AP) * 4)   // 139264 bytes

__device__ __forceinline__ void at_load_tile(uint32_t smb, int buf, int kt, int tid,
                                             size_t bS, int hoff,
                                             const float* __restrict__ kh,
                                             const float* __restrict__ kl,
                                             const float* __restrict__ vr) {
    int k0 = kt * 64;
#pragma unroll
    for (int t = 0; t < 4; t++) {
        int idx = tid + t * 256;
        int r = idx >> 4, c = (idx & 15) << 2;
        size_t g = (size_t)(bS + k0 + r) * Ed + hoff + c;
        uint32_t soff = (uint32_t)(r * AP + c) * 4;
        cp_async16(smb + SM_KH(buf) * 4 + soff, kh + g);
        cp_async16(smb + SM_KL(buf) * 4 + soff, kl + g);
        cp_async16(smb + SM_VS(buf) * 4 + soff, vr + g);
    }
}

__global__ __launch_bounds__(256, 1)
void attention_mma2_kernel(const float* __restrict__ qkv,
                           const float* __restrict__ kh,
                           const float* __restrict__ kl,
                           const float* __restrict__ vr,
                           const unsigned long long* __restrict__ mbits,
                           float* __restrict__ ctx) {
    extern __shared__ float sm[];
    float* Ps = sm + SM_PS;

    const int qt = blockIdx.x, bh = blockIdx.y;
    const int b = bh >> 4, h = bh & 15;
    const int tid = threadIdx.x, lane = tid & 31, warp = tid >> 5;
    const int gid = lane >> 2, tig = lane & 3;
    const int q0 = qt * 128, hoff = h * Dh;
    const size_t bS = (size_t)b * Sq;
    const int wrow = warp * 16;
    const int r0 = wrow + gid, r1 = r0 + 8;
    const uint32_t smb = smem_u32(sm);

    // stage Q tile into Ps
#pragma unroll
    for (int t = 0; t < 8; t++) {
        int idx = tid + t * 256;
        int r = idx >> 4, c = (idx & 15) << 2;
        float4 v = *(const float4*)&qkv[(bS + q0 + r) * E3 + hoff + c];
        *(float4*)&Ps[r * AP + c] = v;
    }
    // prologue: tile 0 -> buffer 0
    at_load_tile(smb, 0, 0, tid, bS, hoff, kh, kl, vr);
    CP_COMMIT();
    __syncthreads();

    // Q fragments hi/lo (register-resident)
    uint32_t qh[8][4], ql[8][4];
#pragma unroll
    for (int kk = 0; kk < 8; kk++) {
        float v0 = Ps[r0 * AP + 8 * kk + tig];
        float v1 = Ps[r1 * AP + 8 * kk + tig];
        float v2 = Ps[r0 * AP + 8 * kk + tig + 4];
        float v3 = Ps[r1 * AP + 8 * kk + tig + 4];
        float h0 = to_tf32(v0), h1 = to_tf32(v1), h2 = to_tf32(v2), h3 = to_tf32(v3);
        qh[kk][0] = __float_as_uint(h0); ql[kk][0] = __float_as_uint(to_tf32(v0 - h0));
        qh[kk][1] = __float_as_uint(h1); ql[kk][1] = __float_as_uint(to_tf32(v1 - h1));
        qh[kk][2] = __float_as_uint(h2); ql[kk][2] = __float_as_uint(to_tf32(v2 - h2));
        qh[kk][3] = __float_as_uint(h3); ql[kk][3] = __float_as_uint(to_tf32(v3 - h3));
    }

    const unsigned long long* mrow0 = mbits + (bS + q0 + r0) * (Sq / 64);
    const unsigned long long* mrow1 = mbits + (bS + q0 + r1) * (Sq / 64);

    float mrw0 = -INFINITY, mrw1 = -INFINITY, lrw0 = 0.f, lrw1 = 0.f;
    float oacc[8][4];
#pragma unroll
    for (int j = 0; j < 8; j++)
#pragma unroll
        for (int r = 0; r < 4; r++) oacc[j][r] = 0.f;

    for (int kt = 0; kt < Sq / 64; kt++) {
        const int buf = kt & 1;
        __syncthreads();   // everyone done reading buffer we're about to refill
        if (kt + 1 < Sq / 64) {
            at_load_tile(smb, buf ^ 1, kt + 1, tid, bS, hoff, kh, kl, vr);
            CP_COMMIT();
            CP_WAIT(1);
        } else {
            CP_WAIT(0);
        }
        __syncthreads();

        const float* KHs = sm + SM_KH(buf);
        const float* KLs = sm + SM_KL(buf);
        const float* Vss = sm + SM_VS(buf);

        unsigned long long mb0 = mrow0[kt];
        unsigned long long mb1 = mrow1[kt];

        // QK^T with 3xTF32 (operands pre-split; pure LDS + MMA)
        float sc[8][4];
#pragma unroll
        for (int j = 0; j < 8; j++)
#pragma unroll
            for (int r = 0; r < 4; r++) sc[j][r] = 0.f;
#pragma unroll
        for (int kk = 0; kk < 8; kk++) {
#pragma unroll
            for (int j = 0; j < 8; j++) {
                const float* hp = &KHs[(8 * j + gid) * AP + 8 * kk + tig];
                const float* lp = &KLs[(8 * j + gid) * AP + 8 * kk + tig];
                uint32_t bhh[2] = { __float_as_uint(hp[0]), __float_as_uint(hp[4]) };
                uint32_t bll[2] = { __float_as_uint(lp[0]), __float_as_uint(lp[4]) };
                mma_tf32(sc[j], qh[kk], bhh);
                mma_tf32(sc[j], ql[kk], bhh);
                mma_tf32(sc[j], qh[kk], bll);
            }
        }

        // scale + mask quirk from bitmask (masked -> literally 1e-9)
#pragma unroll
        for (int j = 0; j < 8; j++) {
            int col = 8 * j + 2 * tig;
            sc[j][0] = ((mb0 >> col) & 1)       ? 1e-9f : sc[j][0] * 0.125f;
            sc[j][1] = ((mb0 >> (col + 1)) & 1) ? 1e-9f : sc[j][1] * 0.125f;
            sc[j][2] = ((mb1 >> col) & 1)       ? 1e-9f : sc[j][2] * 0.125f;
            sc[j][3] = ((mb1 >> (col + 1)) & 1) ? 1e-9f : sc[j][3] * 0.125f;
        }

        // online softmax
        float mx0 = -INFINITY, mx1 = -INFINITY;
#pragma unroll
        for (int j = 0; j < 8; j++) {
            mx0 = fmaxf(mx0, fmaxf(sc[j][0], sc[j][1]));
            mx1 = fmaxf(mx1, fmaxf(sc[j][2], sc[j][3]));
        }
        mx0 = fmaxf(mx0, __shfl_xor_sync(0xffffffffu, mx0, 1));
        mx0 = fmaxf(mx0, __shfl_xor_sync(0xffffffffu, mx0, 2));
        mx1 = fmaxf(mx1, __shfl_xor_sync(0xffffffffu, mx1, 1));
        mx1 = fmaxf(mx1, __shfl_xor_sync(0xffffffffu, mx1, 2));
        float mn0 = fmaxf(mrw0, mx0), mn1 = fmaxf(mrw1, mx1);
        float corr0 = __expf(mrw0 - mn0), corr1 = __expf(mrw1 - mn1);
        float sum0 = 0.f, sum1 = 0.f;
#pragma unroll
        for (int j = 0; j < 8; j++) {
            sc[j][0] = __expf(sc[j][0] - mn0);
            sc[j][1] = __expf(sc[j][1] - mn0);
            sc[j][2] = __expf(sc[j][2] - mn1);
            sc[j][3] = __expf(sc[j][3] - mn1);
            sum0 += sc[j][0] + sc[j][1];
            sum1 += sc[j][2] + sc[j][3];
        }
        sum0 += __shfl_xor_sync(0xffffffffu, sum0, 1);
        sum0 += __shfl_xor_sync(0xffffffffu, sum0, 2);
        sum1 += __shfl_xor_sync(0xffffffffu, sum1, 1);
        sum1 += __shfl_xor_sync(0xffffffffu, sum1, 2);
        lrw0 = lrw0 * corr0 + sum0;
        lrw1 = lrw1 * corr1 + sum1;
        mrw0 = mn0; mrw1 = mn1;
#pragma unroll
        for (int j = 0; j < 8; j++) {
            oacc[j][0] *= corr0; oacc[j][1] *= corr0;
            oacc[j][2] *= corr1; oacc[j][3] *= corr1;
        }
        // P (tf32-rounded) to per-warp rows of Ps
#pragma unroll
        for (int j = 0; j < 8; j++) {
            int col = 8 * j + 2 * tig;
            float2 p0, p1;
            p0.x = to_tf32(sc[j][0]); p0.y = to_tf32(sc[j][1]);
            p1.x = to_tf32(sc[j][2]); p1.y = to_tf32(sc[j][3]);
            *(float2*)&Ps[r0 * AP + col] = p0;
            *(float2*)&Ps[r1 * AP + col] = p1;
        }
        __syncwarp();

        // PV: out += P(16x64) * V(64x64); V read transposed
#pragma unroll
        for (int kk = 0; kk < 8; kk++) {
            uint32_t a[4];
            a[0] = __float_as_uint(Ps[r0 * AP + 8 * kk + tig]);
            a[1] = __float_as_uint(Ps[r1 * AP + 8 * kk + tig]);
            a[2] = __float_as_uint(Ps[r0 * AP + 8 * kk + tig + 4]);
            a[3] = __float_as_uint(Ps[r1 * AP + 8 * kk + tig + 4]);
#pragma unroll
            for (int j = 0; j < 8; j++) {
                uint32_t bb[2] = {
                    __float_as_uint(Vss[(8 * kk + tig) * AP + 8 * j + gid]),
                    __float_as_uint(Vss[(8 * kk + tig + 4) * AP + 8 * j + gid])
                };
                mma_tf32(oacc[j], a, bb);
            }
        }
    }

    // epilogue: normalize, tf32-round, write ctx
    float inv0 = 1.f / lrw0, inv1 = 1.f / lrw1;
    const size_t row0 = bS + q0 + wrow + gid;
#pragma unroll
    for (int j = 0; j < 8; j++) {
        int col = hoff + 8 * j + 2 * tig;
        float2 o0, o1;
        o0.x = to_tf32(oacc[j][0] * inv0); o0.y = to_tf32(oacc[j][1] * inv0);
        o1.x = to_tf32(oacc[j][2] * inv1); o1.y = to_tf32(oacc[j][3] * inv1);
        *(float2*)&ctx[row0 * Ed + col]       = o0;
        *(float2*)&ctx[(row0 + 8) * Ed + col] = o1;
    }
}

// ---------------- launcher ----------------
extern "C" void kernel_launch(void* const* d_in, const int* in_sizes, int n_in,
                              void* d_out, int out_size) {
    const float* x        = (const float*)d_in[0];
    const void*  amask    = d_in[1];
    const float* w_kernel = (const float*)d_in[2];
    const float* w_bias   = (const float*)d_in[3];
    const float* fc_kernel= (const float*)d_in[4];
    const float* fc_bias  = (const float*)d_in[5];
    float* out = (float*)d_out;

    float *qkv, *ctx, *xr, *bt, *bt2, *kh, *kl, *vr;
    unsigned long long* mbits;
    cudaGetSymbolAddress((void**)&qkv, g_qkv);
    cudaGetSymbolAddress((void**)&ctx, g_ctx);
    cudaGetSymbolAddress((void**)&xr,  g_xr);
    cudaGetSymbolAddress((void**)&bt,  g_bt);
    cudaGetSymbolAddress((void**)&bt2, g_bt2);
    cudaGetSymbolAddress((void**)&kh,  g_kh);
    cudaGetSymbolAddress((void**)&kl,  g_kl);
    cudaGetSymbolAddress((void**)&vr,  g_vr);
    cudaGetSymbolAddress((void**)&mbits, g_mbits);

    // 1. mask dtype detection + bit packing
    long long nscan = in_sizes[1];
    if (nscan > (1 << 20)) nscan = (1 << 20);
    detect_mask_mode_kernel<<<1, 256>>>((const unsigned char*)amask, nscan);
    {
        int nwords = Bz * Sq * (Sq / 64);   // 131072
        pack_mask_kernel<<<nwords / 256, 256>>>(amask, mbits);
    }

    // 2. tf32 pre-rounding of GEMM operands
    {
        int n4 = (Mrows * Ed) / 4;
        round_copy_kernel<<<(n4 + 255) / 256, 256>>>((const float4*)x, (float4*)xr, n4);
        transpose_round_kernel<<<dim3(E3 / 32, Ed / 32), dim3(32, 8)>>>(w_kernel, bt, Ed, E3);
        transpose_round_kernel<<<dim3(Ed / 32, Ed / 32), dim3(32, 8)>>>(fc_kernel, bt2, Ed, Ed);
    }

    // 3. QKV projection (mma.sync tf32)
    {
        dim3 grid(E3 / 128, Mrows / 128);
        tf32_mma_gemm<<<grid, 256>>>(xr, bt, w_bias, qkv, E3, Ed);
    }

    // 4. K hi/lo split + V rounding pre-pass
    {
        int n = Mrows * (Ed / 4);
        prep_kv_kernel<<<(n + 255) / 256, 256>>>(qkv, kh, kl, vr);
    }

    // 5. tensor-core flash attention v2
    {
        cudaFuncSetAttribute(attention_mma2_kernel,
                             cudaFuncAttributeMaxDynamicSharedMemorySize, AT2_SMEM);
        dim3 grid(Sq / 128, Bz * Hh);
        attention_mma2_kernel<<<grid, 256, AT2_SMEM>>>(qkv, kh, kl, vr, mbits, ctx);
    }

    // 6. output projection (mma.sync tf32)
    {
        dim3 grid(Ed / 128, Mrows / 128);
        tf32_mma_gemm<<<grid, 256>>>(ctx, bt2, fc_bias, out, Ed, Ed);
    }
}

// round 7
// speedup vs baseline: 2.5511x; 1.5416x over previous
#include <cuda_runtime.h>
#include <cuda_fp16.h>
#include <cstdint>
#include <math.h>

// Problem constants
#define Bz 2
#define Sq 2048
#define Ed 1024
#define Hh 16
#define Dh 64
#define E3 3072
#define Mrows (Bz*Sq)   // 4096

// ---------------- device scratch ----------------
__device__ __align__(16) float g_qkv[Bz * Sq * E3];     // GEMM1 out (fp32)
__device__ __align__(16) __half g_xh [Bz * Sq * Ed];    // x fp16
__device__ __align__(16) __half g_wh [E3 * Ed];         // w_kernel^T fp16
__device__ __align__(16) __half g_w2h[Ed * Ed];         // fc_kernel^T fp16
__device__ __align__(16) __half g_kh2[Bz * Sq * Ed];    // K fp16 (token-major)
__device__ __align__(16) __half g_vt [Bz * Hh * Dh * Sq]; // V^T fp16: [bh][d][s]
__device__ __align__(16) __half g_ctxh[Bz * Sq * Ed];   // attention out fp16
__device__ __align__(16) unsigned long long g_mbits[(size_t)Bz * Sq * Sq / 64];
__device__ int   g_mask_mode;

// ---------------- base-PTX helpers ----------------
__device__ __forceinline__ uint32_t smem_u32(const void* p) {
    uint32_t a;
    asm("{ .reg .u64 t; cvta.to.shared.u64 t, %1; cvt.u32.u64 %0, t; }" : "=r"(a) : "l"(p));
    return a;
}
__device__ __forceinline__ void cp_async16(uint32_t dst, const void* src) {
    asm volatile("cp.async.cg.shared.global [%0], [%1], 16;" :: "r"(dst), "l"(src));
}
#define CP_COMMIT() asm volatile("cp.async.commit_group;" ::: "memory")
#define CP_WAIT(n)  asm volatile("cp.async.wait_group %0;" :: "n"(n) : "memory")

// D(16x8,f32) += A(16x16,f16,row) * B(16x8,f16,col)
__device__ __forceinline__ void mma_f16(float* d, const uint32_t* a, uint32_t b0, uint32_t b1) {
    asm volatile("mma.sync.aligned.m16n8k16.row.col.f32.f16.f16.f32 "
                 "{%0,%1,%2,%3}, {%4,%5,%6,%7}, {%8,%9}, {%0,%1,%2,%3};"
                 : "+f"(d[0]), "+f"(d[1]), "+f"(d[2]), "+f"(d[3])
                 : "r"(a[0]), "r"(a[1]), "r"(a[2]), "r"(a[3]), "r"(b0), "r"(b1));
}
// pack two floats -> half2 {lo, hi} (rn)
__device__ __forceinline__ uint32_t pack_h2(float lo, float hi) {
    uint32_t r; asm("cvt.rn.f16x2.f32 %0, %1, %2;" : "=r"(r) : "f"(hi), "f"(lo)); return r;
}

// ---------------- mask dtype detector (proven) ----------------
__global__ void detect_mask_mode_kernel(const unsigned char* __restrict__ m, long long nbytes) {
    __shared__ int cnt[5];
    if (threadIdx.x < 5) cnt[threadIdx.x] = 0;
    __syncthreads();
    int local[5] = {0, 0, 0, 0, 0};
    for (long long i = threadIdx.x; i < nbytes; i += blockDim.x) {
        unsigned char v = m[i];
        if (v) { local[(int)(i & 3)]++; if (v != 1) local[4]++; }
    }
#pragma unroll
    for (int j = 0; j < 5; j++) if (local[j]) atomicAdd(&cnt[j], local[j]);
    __syncthreads();
    if (threadIdx.x == 0) {
        int c0 = cnt[0], c1 = cnt[1], weird = cnt[4];
        int mode;
        if (c1 == 0 && cnt[2] == 0 && cnt[3] == 0) mode = 1;
        else if (c0 == 0 && c1 == 0)               mode = 2;
        else if (weird > 0)                        mode = 3;
        else                                       mode = 0;
        g_mask_mode = mode;
    }
}

// ---------------- mask bit-packing (proven in R6) ----------------
__global__ void pack_mask_kernel(const void* __restrict__ mask,
                                 unsigned long long* __restrict__ mbits) {
    int w = blockIdx.x * blockDim.x + threadIdx.x;
    int mode = g_mask_mode;
    unsigned long long bits = 0;
    if (mode == 0) {
        const uint4* p = (const uint4*)((const unsigned char*)mask + (size_t)w * 64);
#pragma unroll
        for (int i = 0; i < 4; i++) {
            uint4 v = p[i];
            uint32_t ws[4] = {v.x, v.y, v.z, v.w};
#pragma unroll
            for (int j = 0; j < 4; j++)
#pragma unroll
                for (int bq = 0; bq < 4; bq++)
                    if ((ws[j] >> (8 * bq)) & 0xFFu)
                        bits |= 1ull << (i * 16 + j * 4 + bq);
        }
    } else if (mode == 1 || mode == 2) {
        const uint4* p = (const uint4*)((const uint32_t*)mask + (size_t)w * 64);
#pragma unroll
        for (int i = 0; i < 16; i++) {
            uint4 v = p[i];
            if (v.x) bits |= 1ull << (i * 4 + 0);
            if (v.y) bits |= 1ull << (i * 4 + 1);
            if (v.z) bits |= 1ull << (i * 4 + 2);
            if (v.w) bits |= 1ull << (i * 4 + 3);
        }
    } else {
        const uint4* p = (const uint4*)((const unsigned short*)mask + (size_t)w * 64);
#pragma unroll
        for (int i = 0; i < 8; i++) {
            uint4 v = p[i];
            uint32_t ws[4] = {v.x, v.y, v.z, v.w};
#pragma unroll
            for (int j = 0; j < 4; j++) {
                if (ws[j] & 0xFFFFu) bits |= 1ull << (i * 8 + j * 2);
                if (ws[j] >> 16)     bits |= 1ull << (i * 8 + j * 2 + 1);
            }
        }
    }
    mbits[w] = bits;
}

// ---------------- fp16 conversion pre-passes ----------------
__global__ void f2h_kernel(const float4* __restrict__ in, uint2* __restrict__ out, int n4) {
    int i = blockIdx.x * blockDim.x + threadIdx.x;
    if (i < n4) {
        float4 v = in[i];
        uint2 o;
        o.x = pack_h2(v.x, v.y);
        o.y = pack_h2(v.z, v.w);
        out[i] = o;
    }
}
// out_h[n*K+k] = rn_fp16(in[k*N+n])
__global__ void transpose_h_kernel(const float* __restrict__ in, __half* __restrict__ out,
                                   int K, int N) {
    __shared__ float t[32][33];
    int n0 = blockIdx.x * 32, k0 = blockIdx.y * 32;
    for (int i = threadIdx.y; i < 32; i += 8)
        t[i][threadIdx.x] = in[(size_t)(k0 + i) * N + n0 + threadIdx.x];
    __syncthreads();
    for (int i = threadIdx.y; i < 32; i += 8)
        out[(size_t)(n0 + i) * K + k0 + threadIdx.x] = __float2half_rn(t[threadIdx.x][i]);
}
// K section of qkv -> fp16 (token-major)
__global__ void prep_k_kernel(const float* __restrict__ qkv, uint2* __restrict__ kh2) {
    int i = blockIdx.x * blockDim.x + threadIdx.x;
    if (i >= Mrows * (Ed / 4)) return;
    int row = i / (Ed / 4), c = (i % (Ed / 4)) * 4;
    float4 k = *(const float4*)&qkv[(size_t)row * E3 + Ed + c];
    uint2 o;
    o.x = pack_h2(k.x, k.y);
    o.y = pack_h2(k.z, k.w);
    kh2[((size_t)row * Ed + c) >> 2] = o;
}
// V section -> transposed per-head fp16: vt[bh][d][s]
__global__ void prep_vt_kernel(const float* __restrict__ qkv, __half* __restrict__ vt) {
    __shared__ float t[32][33];
    int s0 = blockIdx.x * 32, d0 = blockIdx.y * 32, bh = blockIdx.z;
    int b = bh >> 4, h = bh & 15;
    for (int i = threadIdx.y; i < 32; i += 8)
        t[i][threadIdx.x] = qkv[(size_t)(b * Sq + s0 + i) * E3 + 2 * Ed + h * Dh + d0 + threadIdx.x];
    __syncthreads();
    for (int i = threadIdx.y; i < 32; i += 8)
        vt[((size_t)bh * Dh + d0 + i) * Sq + s0 + threadIdx.x] = __float2half_rn(t[threadIdx.x][i]);
}

// ---------------- fp16 mma.sync GEMM: C = A * Bt^T + bias (fp32 out) ------------
// A: (M,K) half row-major. Bt: (N,K) half row-major. K=1024.
// CTA 128x128, 8 warps (4x2), warp 32x64 = 2x8 m16n8k16 atoms. BK=32 halves,
// double-buffered cp.async. Row stride 40 halves (conflict-free frag LDS).
#define GLD 40
#define GBK 32

__global__ __launch_bounds__(256, 2)
void hgemm_kernel(const __half* __restrict__ A, const __half* __restrict__ Bt,
                  const float* __restrict__ bias, float* __restrict__ C,
                  int N, int K)
{
    __shared__ __half As[2][128 * GLD];
    __shared__ __half Bs[2][128 * GLD];

    const int tid = threadIdx.x;
    const int warp = tid >> 5, lane = tid & 31;
    const int gid = lane >> 2, tig = lane & 3;
    const int m0 = blockIdx.y * 128, n0 = blockIdx.x * 128;
    const int wm0 = (warp & 3) * 32;
    const int wn0 = (warp >> 2) * 64;

    const __half* Ab = A + (size_t)m0 * K;
    const __half* Bb = Bt + (size_t)n0 * K;

    float acc[2][8][4];
#pragma unroll
    for (int i = 0; i < 2; i++)
#pragma unroll
        for (int j = 0; j < 8; j++)
#pragma unroll
            for (int r = 0; r < 4; r++) acc[i][j][r] = 0.f;

    // loads: 512 16B-chunks per matrix per stage, 2 per thread
    const int lr0 = tid >> 2,          lc0 = (tid & 3) * 8;
    const int lr1 = (tid + 256) >> 2,  lc1 = (tid & 3) * 8;

    const int NS = K / GBK;   // 32

    {
        uint32_t asb = smem_u32(&As[0][0]);
        uint32_t bsb = smem_u32(&Bs[0][0]);
        cp_async16(asb + (lr0 * GLD + lc0) * 2, Ab + (size_t)lr0 * K + lc0);
        cp_async16(asb + (lr1 * GLD + lc1) * 2, Ab + (size_t)lr1 * K + lc1);
        cp_async16(bsb + (lr0 * GLD + lc0) * 2, Bb + (size_t)lr0 * K + lc0);
        cp_async16(bsb + (lr1 * GLD + lc1) * 2, Bb + (size_t)lr1 * K + lc1);
        CP_COMMIT();
    }

    for (int s = 0; s < NS; ++s) {
        if (s + 1 < NS) {
            int buf = (s + 1) & 1;
            int kb = (s + 1) * GBK;
            uint32_t asb = smem_u32(&As[buf][0]);
            uint32_t bsb = smem_u32(&Bs[buf][0]);
            cp_async16(asb + (lr0 * GLD + lc0) * 2, Ab + (size_t)lr0 * K + kb + lc0);
            cp_async16(asb + (lr1 * GLD + lc1) * 2, Ab + (size_t)lr1 * K + kb + lc1);
            cp_async16(bsb + (lr0 * GLD + lc0) * 2, Bb + (size_t)lr0 * K + kb + lc0);
            cp_async16(bsb + (lr1 * GLD + lc1) * 2, Bb + (size_t)lr1 * K + kb + lc1);
            CP_COMMIT();
            CP_WAIT(1);
        } else {
            CP_WAIT(0);
        }
        __syncthreads();

        const __half* as = As[s & 1];
        const __half* bs = Bs[s & 1];
#pragma unroll
        for (int kk = 0; kk < GBK; kk += 16) {
            uint32_t afr[2][4];
#pragma unroll
            for (int i = 0; i < 2; i++) {
                int m = wm0 + 16 * i + gid;
                afr[i][0] = *(const uint32_t*)&as[m * GLD + kk + 2 * tig];
                afr[i][1] = *(const uint32_t*)&as[(m + 8) * GLD + kk + 2 * tig];
                afr[i][2] = *(const uint32_t*)&as[m * GLD + kk + 8 + 2 * tig];
                afr[i][3] = *(const uint32_t*)&as[(m + 8) * GLD + kk + 8 + 2 * tig];
            }
#pragma unroll
            for (int j = 0; j < 8; j++) {
                int n = wn0 + 8 * j + gid;
                uint32_t b0 = *(const uint32_t*)&bs[n * GLD + kk + 2 * tig];
                uint32_t b1 = *(const uint32_t*)&bs[n * GLD + kk + 8 + 2 * tig];
                mma_f16(acc[0][j], afr[0], b0, b1);
                mma_f16(acc[1][j], afr[1], b0, b1);
            }
        }
        __syncthreads();
    }

#pragma unroll
    for (int i = 0; i < 2; i++) {
        int row = m0 + wm0 + 16 * i + gid;
#pragma unroll
        for (int j = 0; j < 8; j++) {
            int col = n0 + wn0 + 8 * j + 2 * tig;
            float2 bv = *(const float2*)&bias[col];
            float2 o0, o1;
            o0.x = acc[i][j][0] + bv.x; o0.y = acc[i][j][1] + bv.y;
            o1.x = acc[i][j][2] + bv.x; o1.y = acc[i][j][3] + bv.y;
            *(float2*)&C[(size_t)row * N + col]       = o0;
            *(float2*)&C[(size_t)(row + 8) * N + col] = o1;
        }
    }
}

// ---------------- fp16 tensor-core flash attention -----------------------
// 2xFP16 QK^T (q hi/lo x k), fp16 PV with P kept in registers (C->A frag map).
// K tile [64 keys][72 halves]; V^T tile [64 d][72 halves]; double-buffered.
#define LK 72
#define KH_BYTES 9216                    // 64*72*2
#define QS_BYTES (128 * 68 * 4)          // fp32 Q staging
#define AT_SMEM (QS_BYTES + 4 * KH_BYTES)  // 71680

__global__ __launch_bounds__(256, 1)
void attention_f16_kernel(const float* __restrict__ qkv,
                          const __half* __restrict__ kh2,
                          const __half* __restrict__ vt,
                          const unsigned long long* __restrict__ mbits,
                          __half* __restrict__ ctxh) {
    extern __shared__ char asmem[];
    float* QS = (float*)asmem;
    const uint32_t kh_smb = smem_u32(asmem + QS_BYTES);
    const uint32_t vt_smb = kh_smb + 2 * KH_BYTES;

    const int qt = blockIdx.x, bh = blockIdx.y;
    const int b = bh >> 4, h = bh & 15;
    const int tid = threadIdx.x, lane = tid & 31, warp = tid >> 5;
    const int gid = lane >> 2, tig = lane & 3;
    const int q0 = qt * 128, hoff = h * Dh;
    const size_t bS = (size_t)b * Sq;
    const int wrow = warp * 16;
    const int r0 = wrow + gid, r1 = r0 + 8;

    // stage Q tile (fp32)
#pragma unroll
    for (int t = 0; t < 8; t++) {
        int idx = tid + t * 256;
        int r = idx >> 4, c = (idx & 15) << 2;
        float4 v = *(const float4*)&qkv[(bS + q0 + r) * E3 + hoff + c];
        *(float4*)&QS[r * 68 + c] = v;
    }
    // prologue: tile 0 -> buffer 0 (KH rows = keys, VT rows = d)
#pragma unroll
    for (int t = 0; t < 2; t++) {
        int idx = tid + t * 256;
        int r = idx >> 3, c = (idx & 7) * 8;
        cp_async16(kh_smb + (r * LK + c) * 2, kh2 + (bS + r) * Ed + hoff + c);
        cp_async16(vt_smb + (r * LK + c) * 2, vt + ((size_t)bh * Dh + r) * Sq + c);
    }
    CP_COMMIT();
    __syncthreads();

    // Q fragments hi/lo (fp16 pairs, register-resident)
    uint32_t qh[4][4], ql[4][4];
#pragma unroll
    for (int kc = 0; kc < 4; kc++) {
        float v0 = QS[r0 * 68 + 16 * kc + 2 * tig];
        float v1 = QS[r0 * 68 + 16 * kc + 2 * tig + 1];
        float v2 = QS[r1 * 68 + 16 * kc + 2 * tig];
        float v3 = QS[r1 * 68 + 16 * kc + 2 * tig + 1];
        float v4 = QS[r0 * 68 + 16 * kc + 8 + 2 * tig];
        float v5 = QS[r0 * 68 + 16 * kc + 8 + 2 * tig + 1];
        float v6 = QS[r1 * 68 + 16 * kc + 8 + 2 * tig];
        float v7 = QS[r1 * 68 + 16 * kc + 8 + 2 * tig + 1];
        qh[kc][0] = pack_h2(v0, v1);
        qh[kc][1] = pack_h2(v2, v3);
        qh[kc][2] = pack_h2(v4, v5);
        qh[kc][3] = pack_h2(v6, v7);
        ql[kc][0] = pack_h2(v0 - __half2float(__float2half_rn(v0)), v1 - __half2float(__float2half_rn(v1)));
        ql[kc][1] = pack_h2(v2 - __half2float(__float2half_rn(v2)), v3 - __half2float(__float2half_rn(v3)));
        ql[kc][2] = pack_h2(v4 - __half2float(__float2half_rn(v4)), v5 - __half2float(__float2half_rn(v5)));
        ql[kc][3] = pack_h2(v6 - __half2float(__float2half_rn(v6)), v7 - __half2float(__float2half_rn(v7)));
    }

    const unsigned long long* mr0 = mbits + (bS + q0 + r0) * (Sq / 64);
    const unsigned long long* mr1 = mbits + (bS + q0 + r1) * (Sq / 64);

    float mrw0 = -INFINITY, mrw1 = -INFINITY, lrw0 = 0.f, lrw1 = 0.f;
    float oacc[8][4];
#pragma unroll
    for (int j = 0; j < 8; j++)
#pragma unroll
        for (int r = 0; r < 4; r++) oacc[j][r] = 0.f;

    for (int kt = 0; kt < Sq / 64; kt++) {
        const int buf = kt & 1;
        __syncthreads();
        if (kt + 1 < Sq / 64) {
            int k0n = (kt + 1) * 64;
            uint32_t kb = kh_smb + (buf ^ 1) * KH_BYTES;
            uint32_t vb = vt_smb + (buf ^ 1) * KH_BYTES;
#pragma unroll
            for (int t = 0; t < 2; t++) {
                int idx = tid + t * 256;
                int r = idx >> 3, c = (idx & 7) * 8;
                cp_async16(kb + (r * LK + c) * 2, kh2 + (bS + k0n + r) * Ed + hoff + c);
                cp_async16(vb + (r * LK + c) * 2, vt + ((size_t)bh * Dh + r) * Sq + k0n + c);
            }
            CP_COMMIT();
            CP_WAIT(1);
        } else {
            CP_WAIT(0);
        }
        __syncthreads();

        const __half* KHs = (const __half*)(asmem + QS_BYTES + buf * KH_BYTES);
        const __half* VTs = (const __half*)(asmem + QS_BYTES + 2 * KH_BYTES + buf * KH_BYTES);

        unsigned long long mb0 = mr0[kt];
        unsigned long long mb1 = mr1[kt];

        // QK^T: 2xFP16 (qh + ql) x kh
        float sc[8][4];
#pragma unroll
        for (int j = 0; j < 8; j++)
#pragma unroll
            for (int r = 0; r < 4; r++) sc[j][r] = 0.f;
#pragma unroll
        for (int kc = 0; kc < 4; kc++) {
#pragma unroll
            for (int j = 0; j < 8; j++) {
                const __half* kp = &KHs[(8 * j + gid) * LK + 16 * kc + 2 * tig];
                uint32_t b0 = *(const uint32_t*)kp;
                uint32_t b1 = *(const uint32_t*)(kp + 8);
                mma_f16(sc[j], qh[kc], b0, b1);
                mma_f16(sc[j], ql[kc], b0, b1);
            }
        }

        // scale + mask quirk (masked -> literally 1e-9)
#pragma unroll
        for (int j = 0; j < 8; j++) {
            int col = 8 * j + 2 * tig;
            sc[j][0] = ((mb0 >> col) & 1)       ? 1e-9f : sc[j][0] * 0.125f;
            sc[j][1] = ((mb0 >> (col + 1)) & 1) ? 1e-9f : sc[j][1] * 0.125f;
            sc[j][2] = ((mb1 >> col) & 1)       ? 1e-9f : sc[j][2] * 0.125f;
            sc[j][3] = ((mb1 >> (col + 1)) & 1) ? 1e-9f : sc[j][3] * 0.125f;
        }

        // online softmax
        float mx0 = -INFINITY, mx1 = -INFINITY;
#pragma unroll
        for (int j = 0; j < 8; j++) {
            mx0 = fmaxf(mx0, fmaxf(sc[j][0], sc[j][1]));
            mx1 = fmaxf(mx1, fmaxf(sc[j][2], sc[j][3]));
        }
        mx0 = fmaxf(mx0, __shfl_xor_sync(0xffffffffu, mx0, 1));
        mx0 = fmaxf(mx0, __shfl_xor_sync(0xffffffffu, mx0, 2));
        mx1 = fmaxf(mx1, __shfl_xor_sync(0xffffffffu, mx1, 1));
        mx1 = fmaxf(mx1, __shfl_xor_sync(0xffffffffu, mx1, 2));
        float mn0 = fmaxf(mrw0, mx0), mn1 = fmaxf(mrw1, mx1);
        float corr0 = __expf(mrw0 - mn0), corr1 = __expf(mrw1 - mn1);
        float sum0 = 0.f, sum1 = 0.f;
#pragma unroll
        for (int j = 0; j < 8; j++) {
            sc[j][0] = __expf(sc[j][0] - mn0);
            sc[j][1] = __expf(sc[j][1] - mn0);
            sc[j][2] = __expf(sc[j][2] - mn1);
            sc[j][3] = __expf(sc[j][3] - mn1);
            sum0 += sc[j][0] + sc[j][1];
            sum1 += sc[j][2] + sc[j][3];
        }
        sum0 += __shfl_xor_sync(0xffffffffu, sum0, 1);
        sum0 += __shfl_xor_sync(0xffffffffu, sum0, 2);
        sum1 += __shfl_xor_sync(0xffffffffu, sum1, 1);
        sum1 += __shfl_xor_sync(0xffffffffu, sum1, 2);
        lrw0 = lrw0 * corr0 + sum0;
        lrw1 = lrw1 * corr1 + sum1;
        mrw0 = mn0; mrw1 = mn1;
#pragma unroll
        for (int j = 0; j < 8; j++) {
            oacc[j][0] *= corr0; oacc[j][1] *= corr0;
            oacc[j][2] *= corr1; oacc[j][3] *= corr1;
        }

        // PV: P stays in registers (QK C-frag == PV A-frag after fp16 pack)
#pragma unroll
        for (int kc = 0; kc < 4; kc++) {
            uint32_t a[4];
            a[0] = pack_h2(sc[2 * kc][0],     sc[2 * kc][1]);
            a[1] = pack_h2(sc[2 * kc][2],     sc[2 * kc][3]);
            a[2] = pack_h2(sc[2 * kc + 1][0], sc[2 * kc + 1][1]);
            a[3] = pack_h2(sc[2 * kc + 1][2], sc[2 * kc + 1][3]);
#pragma unroll
            for (int j = 0; j < 8; j++) {
                const __half* vp = &VTs[(8 * j + gid) * LK + 16 * kc + 2 * tig];
                uint32_t b0 = *(const uint32_t*)vp;
                uint32_t b1 = *(const uint32_t*)(vp + 8);
                mma_f16(oacc[j], a, b0, b1);
            }
        }
    }

    // epilogue: normalize, write ctx as fp16 (feeds output GEMM)
    float inv0 = 1.f / lrw0, inv1 = 1.f / lrw1;
    const size_t row0 = bS + q0 + wrow + gid;
#pragma unroll
    for (int j = 0; j < 8; j++) {
        int col = hoff + 8 * j + 2 * tig;
        *(uint32_t*)&ctxh[row0 * Ed + col] =
            pack_h2(oacc[j][0] * inv0, oacc[j][1] * inv0);
        *(uint32_t*)&ctxh[(row0 + 8) * Ed + col] =
            pack_h2(oacc[j][2] * inv1, oacc[j][3] * inv1);
    }
}

// ---------------- launcher ----------------
extern "C" void kernel_launch(void* const* d_in, const int* in_sizes, int n_in,
                              void* d_out, int out_size) {
    const float* x        = (const float*)d_in[0];
    const void*  amask    = d_in[1];
    const float* w_kernel = (const float*)d_in[2];
    const float* w_bias   = (const float*)d_in[3];
    const float* fc_kernel= (const float*)d_in[4];
    const float* fc_bias  = (const float*)d_in[5];
    float* out = (float*)d_out;

    float* qkv; __half *xh, *wh, *w2h, *kh2, *vt, *ctxh;
    unsigned long long* mbits;
    cudaGetSymbolAddress((void**)&qkv,  g_qkv);
    cudaGetSymbolAddress((void**)&xh,   g_xh);
    cudaGetSymbolAddress((void**)&wh,   g_wh);
    cudaGetSymbolAddress((void**)&w2h,  g_w2h);
    cudaGetSymbolAddress((void**)&kh2,  g_kh2);
    cudaGetSymbolAddress((void**)&vt,   g_vt);
    cudaGetSymbolAddress((void**)&ctxh, g_ctxh);
    cudaGetSymbolAddress((void**)&mbits, g_mbits);

    // 1. mask dtype detection + bit packing
    long long nscan = in_sizes[1];
    if (nscan > (1 << 20)) nscan = (1 << 20);
    detect_mask_mode_kernel<<<1, 256>>>((const unsigned char*)amask, nscan);
    pack_mask_kernel<<<(Bz * Sq * (Sq / 64)) / 256, 256>>>(amask, mbits);

    // 2. fp16 conversions: x, w^T, fc^T
    {
        int n4 = (Mrows * Ed) / 4;
        f2h_kernel<<<(n4 + 255) / 256, 256>>>((const float4*)x, (uint2*)xh, n4);
        transpose_h_kernel<<<dim3(E3 / 32, Ed / 32), dim3(32, 8)>>>(w_kernel, wh, Ed, E3);
        transpose_h_kernel<<<dim3(Ed / 32, Ed / 32), dim3(32, 8)>>>(fc_kernel, w2h, Ed, Ed);
    }

    // 3. QKV projection (fp16 mma m16n8k16)
    hgemm_kernel<<<dim3(E3 / 128, Mrows / 128), 256>>>(xh, wh, w_bias, qkv, E3, Ed);

    // 4. K fp16 + V^T fp16 pre-pass
    {
        int n = Mrows * (Ed / 4);
        prep_k_kernel<<<(n + 255) / 256, 256>>>(qkv, (uint2*)kh2);
        prep_vt_kernel<<<dim3(Sq / 32, Dh / 32, Bz * Hh), dim3(32, 8)>>>(qkv, vt);
    }

    // 5. fp16 tensor-core flash attention
    {
        cudaFuncSetAttribute(attention_f16_kernel,
                             cudaFuncAttributeMaxDynamicSharedMemorySize, AT_SMEM);
        dim3 grid(Sq / 128, Bz * Hh);
        attention_f16_kernel<<<grid, 256, AT_SMEM>>>(qkv, kh2, vt, mbits, ctxh);
    }

    // 6. output projection (fp16 mma)
    hgemm_kernel<<<dim3(Ed / 128, Mrows / 128), 256>>>(ctxh, w2h, fc_bias, out, Ed, Ed);
}

// round 8
// speedup vs baseline: 2.8209x; 1.1057x over previous
#include <cuda_runtime.h>
#include <cuda_fp16.h>
#include <cstdint>
#include <math.h>

// Problem constants
#define Bz 2
#define Sq 2048
#define Ed 1024
#define Hh 16
#define Dh 64
#define E3 3072
#define Mrows (Bz*Sq)   // 4096

// score domain: y = (q.k) * 0.125 * log2(e); folded into Q at prep time
#define QSCALE 0.18033688011112042f
#define MASKC  1.4426950408889634e-9f   // 1e-9 * log2(e)

// ---------------- device scratch ----------------
__device__ __align__(16) float g_qkv[Bz * Sq * E3];     // GEMM1 out (fp32)
__device__ __align__(16) __half g_xh [Bz * Sq * Ed];    // x fp16
__device__ __align__(16) __half g_wh [E3 * Ed];         // w_kernel^T fp16
__device__ __align__(16) __half g_w2h[Ed * Ed];         // fc_kernel^T fp16
__device__ __align__(16) __half g_qh2[Bz * Sq * Ed];    // Q fp16, pre-scaled by QSCALE
__device__ __align__(16) __half g_kh2[Bz * Sq * Ed];    // K fp16
__device__ __align__(16) __half g_vt [Bz * Hh * Dh * Sq]; // V^T fp16: [bh][d][s]
__device__ __align__(16) __half g_ctxh[Bz * Sq * Ed];   // attention out fp16
__device__ __align__(16) unsigned long long g_mbits[(size_t)Bz * Sq * Sq / 64];
__device__ int   g_mask_mode;

// ---------------- base-PTX helpers ----------------
__device__ __forceinline__ uint32_t smem_u32(const void* p) {
    uint32_t a;
    asm("{ .reg .u64 t; cvta.to.shared.u64 t, %1; cvt.u32.u64 %0, t; }" : "=r"(a) : "l"(p));
    return a;
}
__device__ __forceinline__ void cp_async16(uint32_t dst, const void* src) {
    asm volatile("cp.async.cg.shared.global [%0], [%1], 16;" :: "r"(dst), "l"(src));
}
#define CP_COMMIT() asm volatile("cp.async.commit_group;" ::: "memory")
#define CP_WAIT(n)  asm volatile("cp.async.wait_group %0;" :: "n"(n) : "memory")

__device__ __forceinline__ void mma_f16(float* d, const uint32_t* a, uint32_t b0, uint32_t b1) {
    asm volatile("mma.sync.aligned.m16n8k16.row.col.f32.f16.f16.f32 "
                 "{%0,%1,%2,%3}, {%4,%5,%6,%7}, {%8,%9}, {%0,%1,%2,%3};"
                 : "+f"(d[0]), "+f"(d[1]), "+f"(d[2]), "+f"(d[3])
                 : "r"(a[0]), "r"(a[1]), "r"(a[2]), "r"(a[3]), "r"(b0), "r"(b1));
}
__device__ __forceinline__ uint32_t pack_h2(float lo, float hi) {
    uint32_t r; asm("cvt.rn.f16x2.f32 %0, %1, %2;" : "=r"(r) : "f"(hi), "f"(lo)); return r;
}
__device__ __forceinline__ uint32_t ex2_h2(uint32_t y) {
    uint32_t r; asm("ex2.approx.f16x2 %0, %1;" : "=r"(r) : "r"(y)); return r;
}

// ---------------- mask dtype detector (proven) ----------------
__global__ void detect_mask_mode_kernel(const unsigned char* __restrict__ m, long long nbytes) {
    __shared__ int cnt[5];
    if (threadIdx.x < 5) cnt[threadIdx.x] = 0;
    __syncthreads();
    int local[5] = {0, 0, 0, 0, 0};
    for (long long i = threadIdx.x; i < nbytes; i += blockDim.x) {
        unsigned char v = m[i];
        if (v) { local[(int)(i & 3)]++; if (v != 1) local[4]++; }
    }
#pragma unroll
    for (int j = 0; j < 5; j++) if (local[j]) atomicAdd(&cnt[j], local[j]);
    __syncthreads();
    if (threadIdx.x == 0) {
        int c0 = cnt[0], c1 = cnt[1], weird = cnt[4];
        int mode;
        if (c1 == 0 && cnt[2] == 0 && cnt[3] == 0) mode = 1;
        else if (c0 == 0 && c1 == 0)               mode = 2;
        else if (weird > 0)                        mode = 3;
        else                                       mode = 0;
        g_mask_mode = mode;
    }
}

// ---------------- mask bit-packing (proven in R6) ----------------
__global__ void pack_mask_kernel(const void* __restrict__ mask,
                                 unsigned long long* __restrict__ mbits) {
    int w = blockIdx.x * blockDim.x + threadIdx.x;
    int mode = g_mask_mode;
    unsigned long long bits = 0;
    if (mode == 0) {
        const uint4* p = (const uint4*)((const unsigned char*)mask + (size_t)w * 64);
#pragma unroll
        for (int i = 0; i < 4; i++) {
            uint4 v = p[i];
            uint32_t ws[4] = {v.x, v.y, v.z, v.w};
#pragma unroll
            for (int j = 0; j < 4; j++)
#pragma unroll
                for (int bq = 0; bq < 4; bq++)
                    if ((ws[j] >> (8 * bq)) & 0xFFu)
                        bits |= 1ull << (i * 16 + j * 4 + bq);
        }
    } else if (mode == 1 || mode == 2) {
        const uint4* p = (const uint4*)((const uint32_t*)mask + (size_t)w * 64);
#pragma unroll
        for (int i = 0; i < 16; i++) {
            uint4 v = p[i];
            if (v.x) bits |= 1ull << (i * 4 + 0);
            if (v.y) bits |= 1ull << (i * 4 + 1);
            if (v.z) bits |= 1ull << (i * 4 + 2);
            if (v.w) bits |= 1ull << (i * 4 + 3);
        }
    } else {
        const uint4* p = (const uint4*)((const unsigned short*)mask + (size_t)w * 64);
#pragma unroll
        for (int i = 0; i < 8; i++) {
            uint4 v = p[i];
            uint32_t ws[4] = {v.x, v.y, v.z, v.w};
#pragma unroll
            for (int j = 0; j < 4; j++) {
                if (ws[j] & 0xFFFFu) bits |= 1ull << (i * 8 + j * 2);
                if (ws[j] >> 16)     bits |= 1ull << (i * 8 + j * 2 + 1);
            }
        }
    }
    mbits[w] = bits;
}

// ---------------- fp16 conversion pre-passes ----------------
__global__ void f2h_kernel(const float4* __restrict__ in, uint2* __restrict__ out, int n4) {
    int i = blockIdx.x * blockDim.x + threadIdx.x;
    if (i < n4) {
        float4 v = in[i];
        uint2 o;
        o.x = pack_h2(v.x, v.y);
        o.y = pack_h2(v.z, v.w);
        out[i] = o;
    }
}
__global__ void transpose_h_kernel(const float* __restrict__ in, __half* __restrict__ out,
                                   int K, int N) {
    __shared__ float t[32][33];
    int n0 = blockIdx.x * 32, k0 = blockIdx.y * 32;
    for (int i = threadIdx.y; i < 32; i += 8)
        t[i][threadIdx.x] = in[(size_t)(k0 + i) * N + n0 + threadIdx.x];
    __syncthreads();
    for (int i = threadIdx.y; i < 32; i += 8)
        out[(size_t)(n0 + i) * K + k0 + threadIdx.x] = __float2half_rn(t[threadIdx.x][i]);
}
// Q (scaled) + K sections of qkv -> fp16 token-major
__global__ void prep_qk_kernel(const float* __restrict__ qkv,
                               uint2* __restrict__ qh2, uint2* __restrict__ kh2) {
    int i = blockIdx.x * blockDim.x + threadIdx.x;
    if (i >= Mrows * (Ed / 4)) return;
    int row = i / (Ed / 4), c = (i % (Ed / 4)) * 4;
    float4 q = *(const float4*)&qkv[(size_t)row * E3 + c];
    float4 k = *(const float4*)&qkv[(size_t)row * E3 + Ed + c];
    uint2 oq, ok;
    oq.x = pack_h2(q.x * QSCALE, q.y * QSCALE);
    oq.y = pack_h2(q.z * QSCALE, q.w * QSCALE);
    ok.x = pack_h2(k.x, k.y);
    ok.y = pack_h2(k.z, k.w);
    qh2[((size_t)row * Ed + c) >> 2] = oq;
    kh2[((size_t)row * Ed + c) >> 2] = ok;
}
// V -> transposed per-head fp16: vt[bh][d][s]
__global__ void prep_vt_kernel(const float* __restrict__ qkv, __half* __restrict__ vt) {
    __shared__ float t[32][33];
    int s0 = blockIdx.x * 32, d0 = blockIdx.y * 32, bh = blockIdx.z;
    int b = bh >> 4, h = bh & 15;
    for (int i = threadIdx.y; i < 32; i += 8)
        t[i][threadIdx.x] = qkv[(size_t)(b * Sq + s0 + i) * E3 + 2 * Ed + h * Dh + d0 + threadIdx.x];
    __syncthreads();
    for (int i = threadIdx.y; i < 32; i += 8)
        vt[((size_t)bh * Dh + d0 + i) * Sq + s0 + threadIdx.x] = __float2half_rn(t[threadIdx.x][i]);
}

// ---------------- fp16 mma.sync GEMM (proven in R7) ----------------
#define GLD 40
#define GBK 32

__global__ __launch_bounds__(256, 2)
void hgemm_kernel(const __half* __restrict__ A, const __half* __restrict__ Bt,
                  const float* __restrict__ bias, float* __restrict__ C,
                  int N, int K)
{
    __shared__ __half As[2][128 * GLD];
    __shared__ __half Bs[2][128 * GLD];

    const int tid = threadIdx.x;
    const int warp = tid >> 5, lane = tid & 31;
    const int gid = lane >> 2, tig = lane & 3;
    const int m0 = blockIdx.y * 128, n0 = blockIdx.x * 128;
    const int wm0 = (warp & 3) * 32;
    const int wn0 = (warp >> 2) * 64;

    const __half* Ab = A + (size_t)m0 * K;
    const __half* Bb = Bt + (size_t)n0 * K;

    float acc[2][8][4];
#pragma unroll
    for (int i = 0; i < 2; i++)
#pragma unroll
        for (int j = 0; j < 8; j++)
#pragma unroll
            for (int r = 0; r < 4; r++) acc[i][j][r] = 0.f;

    const int lr0 = tid >> 2,          lc0 = (tid & 3) * 8;
    const int lr1 = (tid + 256) >> 2,  lc1 = (tid & 3) * 8;

    const int NS = K / GBK;

    {
        uint32_t asb = smem_u32(&As[0][0]);
        uint32_t bsb = smem_u32(&Bs[0][0]);
        cp_async16(asb + (lr0 * GLD + lc0) * 2, Ab + (size_t)lr0 * K + lc0);
        cp_async16(asb + (lr1 * GLD + lc1) * 2, Ab + (size_t)lr1 * K + lc1);
        cp_async16(bsb + (lr0 * GLD + lc0) * 2, Bb + (size_t)lr0 * K + lc0);
        cp_async16(bsb + (lr1 * GLD + lc1) * 2, Bb + (size_t)lr1 * K + lc1);
        CP_COMMIT();
    }

    for (int s = 0; s < NS; ++s) {
        if (s + 1 < NS) {
            int buf = (s + 1) & 1;
            int kb = (s + 1) * GBK;
            uint32_t asb = smem_u32(&As[buf][0]);
            uint32_t bsb = smem_u32(&Bs[buf][0]);
            cp_async16(asb + (lr0 * GLD + lc0) * 2, Ab + (size_t)lr0 * K + kb + lc0);
            cp_async16(asb + (lr1 * GLD + lc1) * 2, Ab + (size_t)lr1 * K + kb + lc1);
            cp_async16(bsb + (lr0 * GLD + lc0) * 2, Bb + (size_t)lr0 * K + kb + lc0);
            cp_async16(bsb + (lr1 * GLD + lc1) * 2, Bb + (size_t)lr1 * K + kb + lc1);
            CP_COMMIT();
            CP_WAIT(1);
        } else {
            CP_WAIT(0);
        }
        __syncthreads();

        const __half* as = As[s & 1];
        const __half* bs = Bs[s & 1];
#pragma unroll
        for (int kk = 0; kk < GBK; kk += 16) {
            uint32_t afr[2][4];
#pragma unroll
            for (int i = 0; i < 2; i++) {
                int m = wm0 + 16 * i + gid;
                afr[i][0] = *(const uint32_t*)&as[m * GLD + kk + 2 * tig];
                afr[i][1] = *(const uint32_t*)&as[(m + 8) * GLD + kk + 2 * tig];
                afr[i][2] = *(const uint32_t*)&as[m * GLD + kk + 8 + 2 * tig];
                afr[i][3] = *(const uint32_t*)&as[(m + 8) * GLD + kk + 8 + 2 * tig];
            }
#pragma unroll
            for (int j = 0; j < 8; j++) {
                int n = wn0 + 8 * j + gid;
                uint32_t b0 = *(const uint32_t*)&bs[n * GLD + kk + 2 * tig];
                uint32_t b1 = *(const uint32_t*)&bs[n * GLD + kk + 8 + 2 * tig];
                mma_f16(acc[0][j], afr[0], b0, b1);
                mma_f16(acc[1][j], afr[1], b0, b1);
            }
        }
        __syncthreads();
    }

#pragma unroll
    for (int i = 0; i < 2; i++) {
        int row = m0 + wm0 + 16 * i + gid;
#pragma unroll
        for (int j = 0; j < 8; j++) {
            int col = n0 + wn0 + 8 * j + 2 * tig;
            float2 bv = *(const float2*)&bias[col];
            float2 o0, o1;
            o0.x = acc[i][j][0] + bv.x; o0.y = acc[i][j][1] + bv.y;
            o1.x = acc[i][j][2] + bv.x; o1.y = acc[i][j][3] + bv.y;
            *(float2*)&C[(size_t)row * N + col]       = o0;
            *(float2*)&C[(size_t)(row + 8) * N + col] = o1;
        }
    }
}

// ---------------- fp16 flash attention v3 ---------------------------------
// 1xFP16 QK (scale folded into Q), fixed-base 2^y softmax via ex2.approx.f16x2,
// denominator via ones-column MMA (same fp16 p as numerator), no rescaling.
// SMEM halves: QH[128*72], KH[2][64*72], VT[2][64*72]
#define LK 72
#define KH_BYTES (64 * LK * 2)             // 9216
#define QH_BYTES (128 * LK * 2)            // 18432
#define AT_SMEM (QH_BYTES + 4 * KH_BYTES)  // 55296

__global__ __launch_bounds__(256, 2)
void attention_f16_kernel(const __half* __restrict__ qh2,
                          const __half* __restrict__ kh2,
                          const __half* __restrict__ vt,
                          const unsigned long long* __restrict__ mbits,
                          __half* __restrict__ ctxh) {
    extern __shared__ char asmem[];
    const uint32_t qh_smb = smem_u32(asmem);
    const uint32_t kh_smb = qh_smb + QH_BYTES;
    const uint32_t vt_smb = kh_smb + 2 * KH_BYTES;
    const __half* QHs = (const __half*)asmem;

    const int qt = blockIdx.x, bh = blockIdx.y;
    const int b = bh >> 4, h = bh & 15;
    const int tid = threadIdx.x, lane = tid & 31, warp = tid >> 5;
    const int gid = lane >> 2, tig = lane & 3;
    const int q0 = qt * 128, hoff = h * Dh;
    const size_t bS = (size_t)b * Sq;
    const int wrow = warp * 16;
    const int r0 = wrow + gid, r1 = r0 + 8;

    // prologue: Q tile + K/V tile 0, one cp.async group
#pragma unroll
    for (int t = 0; t < 4; t++) {
        int idx = tid + t * 256;
        int r = idx >> 3, c = (idx & 7) * 8;
        cp_async16(qh_smb + (r * LK + c) * 2, qh2 + (bS + q0 + r) * Ed + hoff + c);
    }
#pragma unroll
    for (int t = 0; t < 2; t++) {
        int idx = tid + t * 256;
        int r = idx >> 3, c = (idx & 7) * 8;
        cp_async16(kh_smb + (r * LK + c) * 2, kh2 + (bS + r) * Ed + hoff + c);
        cp_async16(vt_smb + (r * LK + c) * 2, vt + ((size_t)bh * Dh + r) * Sq + c);
    }
    CP_COMMIT();
    CP_WAIT(0);
    __syncthreads();

    // Q fragments (pre-scaled fp16): raw LDS, no conversion
    uint32_t qf[4][4];
#pragma unroll
    for (int kc = 0; kc < 4; kc++) {
        qf[kc][0] = *(const uint32_t*)&QHs[r0 * LK + 16 * kc + 2 * tig];
        qf[kc][1] = *(const uint32_t*)&QHs[r1 * LK + 16 * kc + 2 * tig];
        qf[kc][2] = *(const uint32_t*)&QHs[r0 * LK + 16 * kc + 8 + 2 * tig];
        qf[kc][3] = *(const uint32_t*)&QHs[r1 * LK + 16 * kc + 8 + 2 * tig];
    }

    const unsigned long long* mr0 = mbits + (bS + q0 + r0) * (Sq / 64);
    const unsigned long long* mr1 = mbits + (bS + q0 + r1) * (Sq / 64);

    float oacc[8][4], osum[4];
#pragma unroll
    for (int j = 0; j < 8; j++)
#pragma unroll
        for (int r = 0; r < 4; r++) oacc[j][r] = 0.f;
#pragma unroll
    for (int r = 0; r < 4; r++) osum[r] = 0.f;

    const uint32_t ONES = 0x3C003C00u;

    for (int kt = 0; kt < Sq / 64; kt++) {
        const int buf = kt & 1;
        __syncthreads();
        if (kt + 1 < Sq / 64) {
            int k0n = (kt + 1) * 64;
            uint32_t kb = kh_smb + (buf ^ 1) * KH_BYTES;
            uint32_t vb = vt_smb + (buf ^ 1) * KH_BYTES;
#pragma unroll
            for (int t = 0; t < 2; t++) {
                int idx = tid + t * 256;
                int r = idx >> 3, c = (idx & 7) * 8;
                cp_async16(kb + (r * LK + c) * 2, kh2 + (bS + k0n + r) * Ed + hoff + c);
                cp_async16(vb + (r * LK + c) * 2, vt + ((size_t)bh * Dh + r) * Sq + k0n + c);
            }
            CP_COMMIT();
            CP_WAIT(1);
        } else {
            CP_WAIT(0);
        }
        __syncthreads();

        const __half* KHs = (const __half*)(asmem + QH_BYTES + buf * KH_BYTES);
        const __half* VTs = (const __half*)(asmem + QH_BYTES + 2 * KH_BYTES + buf * KH_BYTES);

        unsigned long long mb0 = mr0[kt];
        unsigned long long mb1 = mr1[kt];

        // QK^T (scores already in 2^-domain units: y = q.k * 0.125 * log2e)
        float sc[8][4];
#pragma unroll
        for (int j = 0; j < 8; j++)
#pragma unroll
            for (int r = 0; r < 4; r++) sc[j][r] = 0.f;
#pragma unroll
        for (int kc = 0; kc < 4; kc++) {
#pragma unroll
            for (int j = 0; j < 8; j++) {
                const __half* kp = &KHs[(8 * j + gid) * LK + 16 * kc + 2 * tig];
                uint32_t b0 = *(const uint32_t*)kp;
                uint32_t b1 = *(const uint32_t*)(kp + 8);
                mma_f16(sc[j], qf[kc], b0, b1);
            }
        }

        // mask quirk + clamp + fp16 pack + 2^y (p pairs = PV A-fragments)
        uint32_t pp[8][2];
#pragma unroll
        for (int j = 0; j < 8; j++) {
            int col = 8 * j + 2 * tig;
            float y00 = ((mb0 >> col) & 1)       ? MASKC : fminf(sc[j][0], 14.f);
            float y01 = ((mb0 >> (col + 1)) & 1) ? MASKC : fminf(sc[j][1], 14.f);
            float y10 = ((mb1 >> col) & 1)       ? MASKC : fminf(sc[j][2], 14.f);
            float y11 = ((mb1 >> (col + 1)) & 1) ? MASKC : fminf(sc[j][3], 14.f);
            pp[j][0] = ex2_h2(pack_h2(y00, y01));
            pp[j][1] = ex2_h2(pack_h2(y10, y11));
        }

        // PV + denominator (ones-column) on tensor pipe
#pragma unroll
        for (int kc = 0; kc < 4; kc++) {
            uint32_t a[4];
            a[0] = pp[2 * kc][0];
            a[1] = pp[2 * kc][1];
            a[2] = pp[2 * kc + 1][0];
            a[3] = pp[2 * kc + 1][1];
#pragma unroll
            for (int j = 0; j < 8; j++) {
                const __half* vp = &VTs[(8 * j + gid) * LK + 16 * kc + 2 * tig];
                uint32_t b0 = *(const uint32_t*)vp;
                uint32_t b1 = *(const uint32_t*)(vp + 8);
                mma_f16(oacc[j], a, b0, b1);
            }
            mma_f16(osum, a, ONES, ONES);
        }
    }

    // epilogue: normalize by ones-MMA rowsums, write ctx fp16
    float inv0 = 1.f / osum[0], inv1 = 1.f / osum[2];
    const size_t row0 = bS + q0 + wrow + gid;
#pragma unroll
    for (int j = 0; j < 8; j++) {
        int col = hoff + 8 * j + 2 * tig;
        *(uint32_t*)&ctxh[row0 * Ed + col] =
            pack_h2(oacc[j][0] * inv0, oacc[j][1] * inv0);
        *(uint32_t*)&ctxh[(row0 + 8) * Ed + col] =
            pack_h2(oacc[j][2] * inv1, oacc[j][3] * inv1);
    }
}

// ---------------- launcher ----------------
extern "C" void kernel_launch(void* const* d_in, const int* in_sizes, int n_in,
                              void* d_out, int out_size) {
    const float* x        = (const float*)d_in[0];
    const void*  amask    = d_in[1];
    const float* w_kernel = (const float*)d_in[2];
    const float* w_bias   = (const float*)d_in[3];
    const float* fc_kernel= (const float*)d_in[4];
    const float* fc_bias  = (const float*)d_in[5];
    float* out = (float*)d_out;

    float* qkv; __half *xh, *wh, *w2h, *qh2, *kh2, *vt, *ctxh;
    unsigned long long* mbits;
    cudaGetSymbolAddress((void**)&qkv,  g_qkv);
    cudaGetSymbolAddress((void**)&xh,   g_xh);
    cudaGetSymbolAddress((void**)&wh,   g_wh);
    cudaGetSymbolAddress((void**)&w2h,  g_w2h);
    cudaGetSymbolAddress((void**)&qh2,  g_qh2);
    cudaGetSymbolAddress((void**)&kh2,  g_kh2);
    cudaGetSymbolAddress((void**)&vt,   g_vt);
    cudaGetSymbolAddress((void**)&ctxh, g_ctxh);
    cudaGetSymbolAddress((void**)&mbits, g_mbits);

    // 1. mask dtype detection + bit packing
    long long nscan = in_sizes[1];
    if (nscan > (1 << 20)) nscan = (1 << 20);
    detect_mask_mode_kernel<<<1, 256>>>((const unsigned char*)amask, nscan);
    pack_mask_kernel<<<(Bz * Sq * (Sq / 64)) / 256, 256>>>(amask, mbits);

    // 2. fp16 conversions: x, w^T, fc^T
    {
        int n4 = (Mrows * Ed) / 4;
        f2h_kernel<<<(n4 + 255) / 256, 256>>>((const float4*)x, (uint2*)xh, n4);
        transpose_h_kernel<<<dim3(E3 / 32, Ed / 32), dim3(32, 8)>>>(w_kernel, wh, Ed, E3);
        transpose_h_kernel<<<dim3(Ed / 32, Ed / 32), dim3(32, 8)>>>(fc_kernel, w2h, Ed, Ed);
    }

    // 3. QKV projection (fp16 mma m16n8k16)
    hgemm_kernel<<<dim3(E3 / 128, Mrows / 128), 256>>>(xh, wh, w_bias, qkv, E3, Ed);

    // 4. Q (pre-scaled) + K fp16, V^T fp16 pre-passes
    {
        int n = Mrows * (Ed / 4);
        prep_qk_kernel<<<(n + 255) / 256, 256>>>(qkv, (uint2*)qh2, (uint2*)kh2);
        prep_vt_kernel<<<dim3(Sq / 32, Dh / 32, Bz * Hh), dim3(32, 8)>>>(qkv, vt);
    }

    // 5. fp16 flash attention v3 (fixed-base ex2, ones-MMA denominator)
    {
        cudaFuncSetAttribute(attention_f16_kernel,
                             cudaFuncAttributeMaxDynamicSharedMemorySize, AT_SMEM);
        dim3 grid(Sq / 128, Bz * Hh);
        attention_f16_kernel<<<grid, 256, AT_SMEM>>>(qh2, kh2, vt, mbits, ctxh);
    }

    // 6. output projection (fp16 mma)
    hgemm_kernel<<<dim3(Ed / 128, Mrows / 128), 256>>>(ctxh, w2h, fc_bias, out, Ed, Ed);
}

// round 9
// speedup vs baseline: 7.7329x; 2.7413x over previous
#include <cuda_runtime.h>
#include <cuda_fp16.h>
#include <cstdint>
#include <math.h>

// Problem constants
#define Bz 2
#define Sq 2048
#define Ed 1024
#define Hh 16
#define Dh 64
#define E3 3072
#define Mrows (Bz*Sq)   // 4096

// score domain: y = (q.k) * 0.125 * log2(e); folded into Q at GEMM epilogue
#define QSCALE 0.18033688011112042f
#define MASKC  1.4426950408889634e-9f   // 1e-9 * log2(e)

// ---------------- device scratch ----------------
__device__ __align__(16) __half g_xh [Bz * Sq * Ed];    // x fp16
__device__ __align__(16) __half g_wh [E3 * Ed];         // w_kernel^T fp16
__device__ __align__(16) __half g_w2h[Ed * Ed];         // fc_kernel^T fp16
__device__ __align__(16) __half g_qh2[Bz * Sq * Ed];    // Q fp16, pre-scaled
__device__ __align__(16) __half g_kh2[Bz * Sq * Ed];    // K fp16
__device__ __align__(16) __half g_vh [Bz * Sq * Ed];    // V fp16 token-major
__device__ __align__(16) __half g_vt [Bz * Hh * Dh * Sq]; // V^T fp16: [bh][d][s]
__device__ __align__(16) __half g_ctxh[Bz * Sq * Ed];   // attention out fp16
__device__ __align__(16) unsigned long long g_mbits[(size_t)Bz * Sq * Sq / 64];

// ---------------- base-PTX helpers ----------------
__device__ __forceinline__ uint32_t smem_u32(const void* p) {
    uint32_t a;
    asm("{ .reg .u64 t; cvta.to.shared.u64 t, %1; cvt.u32.u64 %0, t; }" : "=r"(a) : "l"(p));
    return a;
}
__device__ __forceinline__ void cp_async16(uint32_t dst, const void* src) {
    asm volatile("cp.async.cg.shared.global [%0], [%1], 16;" :: "r"(dst), "l"(src));
}
#define CP_COMMIT() asm volatile("cp.async.commit_group;" ::: "memory")
#define CP_WAIT(n)  asm volatile("cp.async.wait_group %0;" :: "n"(n) : "memory")

__device__ __forceinline__ void mma_f16(float* d, const uint32_t* a, uint32_t b0, uint32_t b1) {
    asm volatile("mma.sync.aligned.m16n8k16.row.col.f32.f16.f16.f32 "
                 "{%0,%1,%2,%3}, {%4,%5,%6,%7}, {%8,%9}, {%0,%1,%2,%3};"
                 : "+f"(d[0]), "+f"(d[1]), "+f"(d[2]), "+f"(d[3])
                 : "r"(a[0]), "r"(a[1]), "r"(a[2]), "r"(a[3]), "r"(b0), "r"(b1));
}
__device__ __forceinline__ uint32_t pack_h2(float lo, float hi) {
    uint32_t r; asm("cvt.rn.f16x2.f32 %0, %1, %2;" : "=r"(r) : "f"(hi), "f"(lo)); return r;
}
__device__ __forceinline__ uint32_t ex2_h2(uint32_t y) {
    uint32_t r; asm("ex2.approx.f16x2 %0, %1;" : "=r"(r) : "r"(y)); return r;
}
#define LDM_X4(r0, r1, r2, r3, addr) \
    asm volatile("ldmatrix.sync.aligned.m8n8.x4.shared.b16 {%0,%1,%2,%3}, [%4];" \
                 : "=r"(r0), "=r"(r1), "=r"(r2), "=r"(r3) : "r"(addr))

// ---------------- mask bit-packing with inline dtype detection ----------------
// Each block classifies the mask dtype from the first 16KB (deterministic),
// then packs its 64-element words. Modes: 0=u8, 1=i32, 2=f32, 3=u16.
__global__ void pack_mask_kernel(const void* __restrict__ mask,
                                 unsigned long long* __restrict__ mbits) {
    __shared__ int cnt[5];
    int tid = threadIdx.x;
    if (tid < 5) cnt[tid] = 0;
    __syncthreads();
    {
        const unsigned char* m8 = (const unsigned char*)mask;
        int loc[5] = {0, 0, 0, 0, 0};
        for (int i = tid; i < 16384; i += 256) {
            unsigned char v = m8[i];
            if (v) { loc[i & 3]++; if (v != 1) loc[4]++; }
        }
#pragma unroll
        for (int j = 0; j < 5; j++) if (loc[j]) atomicAdd(&cnt[j], loc[j]);
    }
    __syncthreads();
    int mode;
    {
        int c0 = cnt[0], c1 = cnt[1], c2 = cnt[2], c3 = cnt[3], weird = cnt[4];
        if (c1 == 0 && c2 == 0 && c3 == 0) mode = 1;
        else if (c0 == 0 && c1 == 0)       mode = 2;
        else if (weird > 0)                mode = 3;
        else                               mode = 0;
    }

    int w = blockIdx.x * blockDim.x + tid;
    unsigned long long bits = 0;
    if (mode == 0) {
        const uint4* p = (const uint4*)((const unsigned char*)mask + (size_t)w * 64);
#pragma unroll
        for (int i = 0; i < 4; i++) {
            uint4 v = p[i];
            uint32_t ws[4] = {v.x, v.y, v.z, v.w};
#pragma unroll
            for (int j = 0; j < 4; j++)
#pragma unroll
                for (int bq = 0; bq < 4; bq++)
                    if ((ws[j] >> (8 * bq)) & 0xFFu)
                        bits |= 1ull << (i * 16 + j * 4 + bq);
        }
    } else if (mode == 1 || mode == 2) {
        const uint4* p = (const uint4*)((const uint32_t*)mask + (size_t)w * 64);
#pragma unroll
        for (int i = 0; i < 16; i++) {
            uint4 v = p[i];
            if (v.x) bits |= 1ull << (i * 4 + 0);
            if (v.y) bits |= 1ull << (i * 4 + 1);
            if (v.z) bits |= 1ull << (i * 4 + 2);
            if (v.w) bits |= 1ull << (i * 4 + 3);
        }
    } else {
        const uint4* p = (const uint4*)((const unsigned short*)mask + (size_t)w * 64);
#pragma unroll
        for (int i = 0; i < 8; i++) {
            uint4 v = p[i];
            uint32_t ws[4] = {v.x, v.y, v.z, v.w};
#pragma unroll
            for (int j = 0; j < 4; j++) {
                if (ws[j] & 0xFFFFu) bits |= 1ull << (i * 8 + j * 2);
                if (ws[j] >> 16)     bits |= 1ull << (i * 8 + j * 2 + 1);
            }
        }
    }
    mbits[w] = bits;
}

// ---------------- fp16 conversion pre-passes ----------------
__global__ void f2h_kernel(const float4* __restrict__ in, uint2* __restrict__ out, int n4) {
    int i = blockIdx.x * blockDim.x + threadIdx.x;
    if (i < n4) {
        float4 v = in[i];
        uint2 o;
        o.x = pack_h2(v.x, v.y);
        o.y = pack_h2(v.z, v.w);
        out[i] = o;
    }
}
__global__ void transpose_h_kernel(const float* __restrict__ in, __half* __restrict__ out,
                                   int K, int N) {
    __shared__ float t[32][33];
    int n0 = blockIdx.x * 32, k0 = blockIdx.y * 32;
    for (int i = threadIdx.y; i < 32; i += 8)
        t[i][threadIdx.x] = in[(size_t)(k0 + i) * N + n0 + threadIdx.x];
    __syncthreads();
    for (int i = threadIdx.y; i < 32; i += 8)
        out[(size_t)(n0 + i) * K + k0 + threadIdx.x] = __float2half_rn(t[threadIdx.x][i]);
}
// V (fp16 token-major) -> transposed per-head fp16: vt[bh][d][s]
__global__ void prep_vt_h_kernel(const __half* __restrict__ vh, __half* __restrict__ vt) {
    __shared__ __half t[32][34];
    int s0 = blockIdx.x * 32, d0 = blockIdx.y * 32, bh = blockIdx.z;
    int b = bh >> 4, h = bh & 15;
    for (int i = threadIdx.y; i < 32; i += 8)
        t[i][threadIdx.x] = vh[(size_t)(b * Sq + s0 + i) * Ed + h * Dh + d0 + threadIdx.x];
    __syncthreads();
    for (int i = threadIdx.y; i < 32; i += 8)
        vt[((size_t)bh * Dh + d0 + i) * Sq + s0 + threadIdx.x] = t[threadIdx.x][i];
}

// ---------------- fp16 mma.sync GEMM with ldmatrix fragments -----------------
// MODE 0: C = A*Bt^T + bias (fp32 out).
// MODE 1: QKV fused epilogue -> qh2 (scaled fp16), kh2, vh. (N=3072 sections)
#define GLD 40
#define GBK 32

template<int MODE>
__global__ __launch_bounds__(256, 2)
void hgemm_k(const __half* __restrict__ A, const __half* __restrict__ Bt,
             const float* __restrict__ bias, float* __restrict__ C,
             __half* __restrict__ qh2, __half* __restrict__ kh2,
             __half* __restrict__ vh, int N, int K)
{
    __shared__ __half As[2][128 * GLD];
    __shared__ __half Bs[2][128 * GLD];

    const int tid = threadIdx.x;
    const int warp = tid >> 5, lane = tid & 31;
    const int gid = lane >> 2, tig = lane & 3;
    const int lr = lane & 7, lq = lane >> 3;
    const int m0 = blockIdx.y * 128, n0 = blockIdx.x * 128;
    const int wm0 = (warp & 3) * 32;
    const int wn0 = (warp >> 2) * 64;

    const __half* Ab = A + (size_t)m0 * K;
    const __half* Bb = Bt + (size_t)n0 * K;

    float acc[2][8][4];
#pragma unroll
    for (int i = 0; i < 2; i++)
#pragma unroll
        for (int j = 0; j < 8; j++)
#pragma unroll
            for (int r = 0; r < 4; r++) acc[i][j][r] = 0.f;

    const int lr0 = tid >> 2,          lc0 = (tid & 3) * 8;
    const int lr1 = (tid + 256) >> 2,  lc1 = (tid & 3) * 8;

    const int NS = K / GBK;

    {
        uint32_t asb = smem_u32(&As[0][0]);
        uint32_t bsb = smem_u32(&Bs[0][0]);
        cp_async16(asb + (lr0 * GLD + lc0) * 2, Ab + (size_t)lr0 * K + lc0);
        cp_async16(asb + (lr1 * GLD + lc1) * 2, Ab + (size_t)lr1 * K + lc1);
        cp_async16(bsb + (lr0 * GLD + lc0) * 2, Bb + (size_t)lr0 * K + lc0);
        cp_async16(bsb + (lr1 * GLD + lc1) * 2, Bb + (size_t)lr1 * K + lc1);
        CP_COMMIT();
    }

    // ldmatrix per-lane address components
    // A (afr[i]): row = wm0+16i + (lq&1)*8 + lr, col = kk + (lq>>1)*8
    // B (pairs jj,jj+1): row = wn0 + 8*(jj + (lq>>1)) + lr, col = kk + (lq&1)*8
    const int a_row_off = (lq & 1) * 8 + lr;
    const int a_col_off = (lq >> 1) * 8;
    const int b_row_off = (lq >> 1) * 8 + lr;
    const int b_col_off = (lq & 1) * 8;

    for (int s = 0; s < NS; ++s) {
        if (s + 1 < NS) {
            int buf = (s + 1) & 1;
            int kb = (s + 1) * GBK;
            uint32_t asb = smem_u32(&As[buf][0]);
            uint32_t bsb = smem_u32(&Bs[buf][0]);
            cp_async16(asb + (lr0 * GLD + lc0) * 2, Ab + (size_t)lr0 * K + kb + lc0);
            cp_async16(asb + (lr1 * GLD + lc1) * 2, Ab + (size_t)lr1 * K + kb + lc1);
            cp_async16(bsb + (lr0 * GLD + lc0) * 2, Bb + (size_t)lr0 * K + kb + lc0);
            cp_async16(bsb + (lr1 * GLD + lc1) * 2, Bb + (size_t)lr1 * K + kb + lc1);
            CP_COMMIT();
            CP_WAIT(1);
        } else {
            CP_WAIT(0);
        }
        __syncthreads();

        uint32_t asb = smem_u32(&As[s & 1][0]);
        uint32_t bsb = smem_u32(&Bs[s & 1][0]);
#pragma unroll
        for (int kk = 0; kk < GBK; kk += 16) {
            uint32_t afr[2][4];
#pragma unroll
            for (int i = 0; i < 2; i++) {
                uint32_t addr = asb + ((wm0 + 16 * i + a_row_off) * GLD + kk + a_col_off) * 2;
                LDM_X4(afr[i][0], afr[i][1], afr[i][2], afr[i][3], addr);
            }
            uint32_t bfr[8][2];
#pragma unroll
            for (int jj = 0; jj < 8; jj += 2) {
                uint32_t addr = bsb + ((wn0 + 8 * jj + b_row_off) * GLD + kk + b_col_off) * 2;
                LDM_X4(bfr[jj][0], bfr[jj][1], bfr[jj + 1][0], bfr[jj + 1][1], addr);
            }
#pragma unroll
            for (int j = 0; j < 8; j++) {
                mma_f16(acc[0][j], afr[0], bfr[j][0], bfr[j][1]);
                mma_f16(acc[1][j], afr[1], bfr[j][0], bfr[j][1]);
            }
        }
        __syncthreads();
    }

#pragma unroll
    for (int i = 0; i < 2; i++) {
        int row = m0 + wm0 + 16 * i + gid;
#pragma unroll
        for (int j = 0; j < 8; j++) {
            int col = n0 + wn0 + 8 * j + 2 * tig;
            float2 bv = *(const float2*)&bias[col];
            float v00 = acc[i][j][0] + bv.x, v01 = acc[i][j][1] + bv.y;
            float v10 = acc[i][j][2] + bv.x, v11 = acc[i][j][3] + bv.y;
            if (MODE == 0) {
                float2 o0, o1;
                o0.x = v00; o0.y = v01; o1.x = v10; o1.y = v11;
                *(float2*)&C[(size_t)row * N + col]       = o0;
                *(float2*)&C[(size_t)(row + 8) * N + col] = o1;
            } else {
                // QKV split epilogue (uniform per block column tile)
                int lc = col & 1023;
                if (col < Ed) {
                    *(uint32_t*)&qh2[(size_t)row * Ed + lc] =
                        pack_h2(v00 * QSCALE, v01 * QSCALE);
                    *(uint32_t*)&qh2[(size_t)(row + 8) * Ed + lc] =
                        pack_h2(v10 * QSCALE, v11 * QSCALE);
                } else if (col < 2 * Ed) {
                    *(uint32_t*)&kh2[(size_t)row * Ed + lc]       = pack_h2(v00, v01);
                    *(uint32_t*)&kh2[(size_t)(row + 8) * Ed + lc] = pack_h2(v10, v11);
                } else {
                    *(uint32_t*)&vh[(size_t)row * Ed + lc]       = pack_h2(v00, v01);
                    *(uint32_t*)&vh[(size_t)(row + 8) * Ed + lc] = pack_h2(v10, v11);
                }
            }
        }
    }
}

// ---------------- fp16 flash attention v4 (ldmatrix fragments) --------------
#define LK 72
#define KH_BYTES (64 * LK * 2)             // 9216
#define QH_BYTES (128 * LK * 2)            // 18432
#define AT_SMEM (QH_BYTES + 4 * KH_BYTES)  // 55296

__global__ __launch_bounds__(256, 2)
void attention_f16_kernel(const __half* __restrict__ qh2,
                          const __half* __restrict__ kh2,
                          const __half* __restrict__ vt,
                          const unsigned long long* __restrict__ mbits,
                          __half* __restrict__ ctxh) {
    extern __shared__ char asmem[];
    const uint32_t qh_smb = smem_u32(asmem);
    const uint32_t kh_smb = qh_smb + QH_BYTES;
    const uint32_t vt_smb = kh_smb + 2 * KH_BYTES;
    const __half* QHs = (const __half*)asmem;

    const int qt = blockIdx.x, bh = blockIdx.y;
    const int b = bh >> 4, h = bh & 15;
    const int tid = threadIdx.x, lane = tid & 31, warp = tid >> 5;
    const int gid = lane >> 2, tig = lane & 3;
    const int lr = lane & 7, lq = lane >> 3;
    const int q0 = qt * 128, hoff = h * Dh;
    const size_t bS = (size_t)b * Sq;
    const int wrow = warp * 16;
    const int r0 = wrow + gid, r1 = r0 + 8;

    // ldmatrix per-lane offset within a K/V tile (j=0, col base 0):
    // matrices: q=0 -> col 0 (b0,kc), q=1 -> col 8 (b1,kc), q=2/3 -> kc+1
    const uint32_t ldm_off = (lr * LK + 8 * lq) * 2;

    // prologue: Q tile + K/V tile 0, one cp.async group
#pragma unroll
    for (int t = 0; t < 4; t++) {
        int idx = tid + t * 256;
        int r = idx >> 3, c = (idx & 7) * 8;
        cp_async16(qh_smb + (r * LK + c) * 2, qh2 + (bS + q0 + r) * Ed + hoff + c);
    }
#pragma unroll
    for (int t = 0; t < 2; t++) {
        int idx = tid + t * 256;
        int r = idx >> 3, c = (idx & 7) * 8;
        cp_async16(kh_smb + (r * LK + c) * 2, kh2 + (bS + r) * Ed + hoff + c);
        cp_async16(vt_smb + (r * LK + c) * 2, vt + ((size_t)bh * Dh + r) * Sq + c);
    }
    CP_COMMIT();
    CP_WAIT(0);
    __syncthreads();

    // Q fragments (pre-scaled fp16)
    uint32_t qf[4][4];
#pragma unroll
    for (int kc = 0; kc < 4; kc++) {
        qf[kc][0] = *(const uint32_t*)&QHs[r0 * LK + 16 * kc + 2 * tig];
        qf[kc][1] = *(const uint32_t*)&QHs[r1 * LK + 16 * kc + 2 * tig];
        qf[kc][2] = *(const uint32_t*)&QHs[r0 * LK + 16 * kc + 8 + 2 * tig];
        qf[kc][3] = *(const uint32_t*)&QHs[r1 * LK + 16 * kc + 8 + 2 * tig];
    }

    const unsigned long long* mr0 = mbits + (bS + q0 + r0) * (Sq / 64);
    const unsigned long long* mr1 = mbits + (bS + q0 + r1) * (Sq / 64);

    float oacc[8][4], osum[4];
#pragma unroll
    for (int j = 0; j < 8; j++)
#pragma unroll
        for (int r = 0; r < 4; r++) oacc[j][r] = 0.f;
#pragma unroll
    for (int r = 0; r < 4; r++) osum[r] = 0.f;

    const uint32_t ONES = 0x3C003C00u;

    for (int kt = 0; kt < Sq / 64; kt++) {
        const int buf = kt & 1;
        __syncthreads();
        if (kt + 1 < Sq / 64) {
            int k0n = (kt + 1) * 64;
            uint32_t kb = kh_smb + (buf ^ 1) * KH_BYTES;
            uint32_t vb = vt_smb + (buf ^ 1) * KH_BYTES;
#pragma unroll
            for (int t = 0; t < 2; t++) {
                int idx = tid + t * 256;
                int r = idx >> 3, c = (idx & 7) * 8;
                cp_async16(kb + (r * LK + c) * 2, kh2 + (bS + k0n + r) * Ed + hoff + c);
                cp_async16(vb + (r * LK + c) * 2, vt + ((size_t)bh * Dh + r) * Sq + k0n + c);
            }
            CP_COMMIT();
            CP_WAIT(1);
        } else {
            CP_WAIT(0);
        }
        __syncthreads();

        const uint32_t kbase = kh_smb + buf * KH_BYTES + ldm_off;
        const uint32_t vbase = vt_smb + buf * KH_BYTES + ldm_off;

        unsigned long long mb0 = mr0[kt];
        unsigned long long mb1 = mr1[kt];

        // QK^T via ldmatrix.x4 B-fragments
        float sc[8][4];
#pragma unroll
        for (int j = 0; j < 8; j++)
#pragma unroll
            for (int r = 0; r < 4; r++) sc[j][r] = 0.f;
#pragma unroll
        for (int j = 0; j < 8; j++) {
            uint32_t kaddr = kbase + j * (8 * LK * 2);
            uint32_t k0r, k1r, k2r, k3r, k4r, k5r, k6r, k7r;
            LDM_X4(k0r, k1r, k2r, k3r, kaddr);
            LDM_X4(k4r, k5r, k6r, k7r, kaddr + 64);
            mma_f16(sc[j], qf[0], k0r, k1r);
            mma_f16(sc[j], qf[1], k2r, k3r);
            mma_f16(sc[j], qf[2], k4r, k5r);
            mma_f16(sc[j], qf[3], k6r, k7r);
        }

        // mask quirk + clamp + fp16 pack + 2^y (p pairs = PV A-fragments)
        uint32_t pp[8][2];
#pragma unroll
        for (int j = 0; j < 8; j++) {
            int col = 8 * j + 2 * tig;
            float y00 = ((mb0 >> col) & 1)       ? MASKC : fminf(sc[j][0], 14.f);
            float y01 = ((mb0 >> (col + 1)) & 1) ? MASKC : fminf(sc[j][1], 14.f);
            float y10 = ((mb1 >> col) & 1)       ? MASKC : fminf(sc[j][2], 14.f);
            float y11 = ((mb1 >> (col + 1)) & 1) ? MASKC : fminf(sc[j][3], 14.f);
            pp[j][0] = ex2_h2(pack_h2(y00, y01));
            pp[j][1] = ex2_h2(pack_h2(y10, y11));
        }

        // denominator via ones-column MMA (per kc chain)
#pragma unroll
        for (int kc = 0; kc < 4; kc++) {
            uint32_t a[4] = { pp[2 * kc][0], pp[2 * kc][1],
                              pp[2 * kc + 1][0], pp[2 * kc + 1][1] };
            mma_f16(osum, a, ONES, ONES);
        }

        // PV via ldmatrix.x4 V^T fragments
#pragma unroll
        for (int j = 0; j < 8; j++) {
            uint32_t vaddr = vbase + j * (8 * LK * 2);
            uint32_t v0r, v1r, v2r, v3r, v4r, v5r, v6r, v7r;
            LDM_X4(v0r, v1r, v2r, v3r, vaddr);
            LDM_X4(v4r, v5r, v6r, v7r, vaddr + 64);
            uint32_t a0[4] = { pp[0][0], pp[0][1], pp[1][0], pp[1][1] };
            uint32_t a1[4] = { pp[2][0], pp[2][1], pp[3][0], pp[3][1] };
            uint32_t a2[4] = { pp[4][0], pp[4][1], pp[5][0], pp[5][1] };
            uint32_t a3[4] = { pp[6][0], pp[6][1], pp[7][0], pp[7][1] };
            mma_f16(oacc[j], a0, v0r, v1r);
            mma_f16(oacc[j], a1, v2r, v3r);
            mma_f16(oacc[j], a2, v4r, v5r);
            mma_f16(oacc[j], a3, v6r, v7r);
        }
    }

    // epilogue: normalize by ones-MMA rowsums, write ctx fp16
    float inv0 = 1.f / osum[0], inv1 = 1.f / osum[2];
    const size_t row0 = bS + q0 + wrow + gid;
#pragma unroll
    for (int j = 0; j < 8; j++) {
        int col = hoff + 8 * j + 2 * tig;
        *(uint32_t*)&ctxh[row0 * Ed + col] =
            pack_h2(oacc[j][0] * inv0, oacc[j][1] * inv0);
        *(uint32_t*)&ctxh[(row0 + 8) * Ed + col] =
            pack_h2(oacc[j][2] * inv1, oacc[j][3] * inv1);
    }
}

// ---------------- launcher ----------------
extern "C" void kernel_launch(void* const* d_in, const int* in_sizes, int n_in,
                              void* d_out, int out_size) {
    const float* x        = (const float*)d_in[0];
    const void*  amask    = d_in[1];
    const float* w_kernel = (const float*)d_in[2];
    const float* w_bias   = (const float*)d_in[3];
    const float* fc_kernel= (const float*)d_in[4];
    const float* fc_bias  = (const float*)d_in[5];
    float* out = (float*)d_out;

    __half *xh, *wh, *w2h, *qh2, *kh2, *vh, *vt, *ctxh;
    unsigned long long* mbits;
    cudaGetSymbolAddress((void**)&xh,   g_xh);
    cudaGetSymbolAddress((void**)&wh,   g_wh);
    cudaGetSymbolAddress((void**)&w2h,  g_w2h);
    cudaGetSymbolAddress((void**)&qh2,  g_qh2);
    cudaGetSymbolAddress((void**)&kh2,  g_kh2);
    cudaGetSymbolAddress((void**)&vh,   g_vh);
    cudaGetSymbolAddress((void**)&vt,   g_vt);
    cudaGetSymbolAddress((void**)&ctxh, g_ctxh);
    cudaGetSymbolAddress((void**)&mbits, g_mbits);

    // 1. x -> fp16
    {
        int n4 = (Mrows * Ed) / 4;
        f2h_kernel<<<(n4 + 255) / 256, 256>>>((const float4*)x, (uint2*)xh, n4);
    }
    // 2. w_kernel^T -> fp16
    transpose_h_kernel<<<dim3(E3 / 32, Ed / 32), dim3(32, 8)>>>(w_kernel, wh, Ed, E3);
    // 3. QKV projection with fused fp16 split epilogue
    hgemm_k<1><<<dim3(E3 / 128, Mrows / 128), 256>>>(
        xh, wh, w_bias, nullptr, qh2, kh2, vh, E3, Ed);
    // 4. V -> per-head transposed fp16
    prep_vt_h_kernel<<<dim3(Sq / 32, Dh / 32, Bz * Hh), dim3(32, 8)>>>(vh, vt);
    // 5. mask bit-packing (inline dtype detection)
    pack_mask_kernel<<<(Bz * Sq * (Sq / 64)) / 256, 256>>>(amask, mbits);
    // 6. fp16 flash attention  <-- ncu -s 5 -c 1 captures this launch
    {
        cudaFuncSetAttribute(attention_f16_kernel,
                             cudaFuncAttributeMaxDynamicSharedMemorySize, AT_SMEM);
        dim3 grid(Sq / 128, Bz * Hh);
        attention_f16_kernel<<<grid, 256, AT_SMEM>>>(qh2, kh2, vt, mbits, ctxh);
    }
    // 7. fc_kernel^T -> fp16
    transpose_h_kernel<<<dim3(Ed / 32, Ed / 32), dim3(32, 8)>>>(fc_kernel, w2h, Ed, Ed);
    // 8. output projection
    hgemm_k<0><<<dim3(Ed / 128, Mrows / 128), 256>>>(
        ctxh, w2h, fc_bias, out, nullptr, nullptr, nullptr, Ed, Ed);
}

// round 10
// speedup vs baseline: 7.9913x; 1.0334x over previous
#include <cuda_runtime.h>
#include <cuda_fp16.h>
#include <cstdint>
#include <math.h>

// Problem constants
#define Bz 2
#define Sq 2048
#define Ed 1024
#define Hh 16
#define Dh 64
#define E3 3072
#define Mrows (Bz*Sq)   // 4096

// score domain: y = (q.k) * 0.125 * log2(e); folded into Q at GEMM epilogue
#define QSCALE 0.18033688011112042f
#define MASKC  1.4426950408889634e-9f   // 1e-9 * log2(e)

// ---------------- device scratch ----------------
__device__ __align__(16) __half g_xh [Bz * Sq * Ed];    // x fp16
__device__ __align__(16) __half g_wh [E3 * Ed];         // w_kernel^T fp16
__device__ __align__(16) __half g_w2h[Ed * Ed];         // fc_kernel^T fp16
__device__ __align__(16) __half g_qh2[Bz * Sq * Ed];    // Q fp16, pre-scaled
__device__ __align__(16) __half g_kh2[Bz * Sq * Ed];    // K fp16
__device__ __align__(16) __half g_vh [Bz * Sq * Ed];    // V fp16 token-major
__device__ __align__(16) __half g_ctxh[Bz * Sq * Ed];   // attention out fp16
__device__ __align__(16) unsigned long long g_mbits[(size_t)Bz * Sq * Sq / 64];

// ---------------- base-PTX helpers ----------------
__device__ __forceinline__ uint32_t smem_u32(const void* p) {
    uint32_t a;
    asm("{ .reg .u64 t; cvta.to.shared.u64 t, %1; cvt.u32.u64 %0, t; }" : "=r"(a) : "l"(p));
    return a;
}
__device__ __forceinline__ void cp_async16(uint32_t dst, const void* src) {
    asm volatile("cp.async.cg.shared.global [%0], [%1], 16;" :: "r"(dst), "l"(src));
}
#define CP_COMMIT() asm volatile("cp.async.commit_group;" ::: "memory")
#define CP_WAIT(n)  asm volatile("cp.async.wait_group %0;" :: "n"(n) : "memory")

__device__ __forceinline__ void mma_f16(float* d, const uint32_t* a, uint32_t b0, uint32_t b1) {
    asm volatile("mma.sync.aligned.m16n8k16.row.col.f32.f16.f16.f32 "
                 "{%0,%1,%2,%3}, {%4,%5,%6,%7}, {%8,%9}, {%0,%1,%2,%3};"
                 : "+f"(d[0]), "+f"(d[1]), "+f"(d[2]), "+f"(d[3])
                 : "r"(a[0]), "r"(a[1]), "r"(a[2]), "r"(a[3]), "r"(b0), "r"(b1));
}
__device__ __forceinline__ uint32_t pack_h2(float lo, float hi) {
    uint32_t r; asm("cvt.rn.f16x2.f32 %0, %1, %2;" : "=r"(r) : "f"(hi), "f"(lo)); return r;
}
__device__ __forceinline__ uint32_t ex2_h2(uint32_t y) {
    uint32_t r; asm("ex2.approx.f16x2 %0, %1;" : "=r"(r) : "r"(y)); return r;
}
#define LDM_X4(r0, r1, r2, r3, addr) \
    asm volatile("ldmatrix.sync.aligned.m8n8.x4.shared.b16 {%0,%1,%2,%3}, [%4];" \
                 : "=r"(r0), "=r"(r1), "=r"(r2), "=r"(r3) : "r"(addr))
#define LDM_X4_T(r0, r1, r2, r3, addr) \
    asm volatile("ldmatrix.sync.aligned.m8n8.x4.trans.shared.b16 {%0,%1,%2,%3}, [%4];" \
                 : "=r"(r0), "=r"(r1), "=r"(r2), "=r"(r3) : "r"(addr))

// ---------------- fused prep kernel ---------------------------------------
// One launch, block ranges: [0,4096) x->fp16 | [4096,7168) w^T | [7168,8192) fc^T
// | [8192,8704) mask bit-pack (with inline dtype detection per block).
#define F2H_BLKS 4096
#define TRW_BLKS 3072
#define TRF_BLKS 1024
#define PACK_BLKS 512
#define PREP_BLKS (F2H_BLKS + TRW_BLKS + TRF_BLKS + PACK_BLKS)

__global__ void prep_all_kernel(const float4* __restrict__ x,
                                const float* __restrict__ wk,
                                const float* __restrict__ fck,
                                const void* __restrict__ mask,
                                uint2* __restrict__ xh,
                                __half* __restrict__ wh,
                                __half* __restrict__ w2h,
                                unsigned long long* __restrict__ mbits) {
    __shared__ float t[32][33];
    __shared__ int cnt[5];
    const int tid = threadIdx.x;
    const int bz = blockIdx.x;

    if (bz < F2H_BLKS) {
        int i = bz * 256 + tid;
        float4 v = x[i];
        uint2 o;
        o.x = pack_h2(v.x, v.y);
        o.y = pack_h2(v.z, v.w);
        xh[i] = o;
    } else if (bz < F2H_BLKS + TRW_BLKS + TRF_BLKS) {
        int b = bz - F2H_BLKS;
        const float* in; __half* outp; int N, bx, by;
        if (b < TRW_BLKS) { in = wk;  outp = wh;  N = E3; bx = b % 96; by = b / 96; }
        else { b -= TRW_BLKS; in = fck; outp = w2h; N = Ed; bx = b & 31; by = b >> 5; }
        int n0 = bx * 32, k0 = by * 32;
        int tx = tid & 31, ty = tid >> 5;
        for (int i = ty; i < 32; i += 8)
            t[i][tx] = in[(size_t)(k0 + i) * N + n0 + tx];
        __syncthreads();
        for (int i = ty; i < 32; i += 8)
            outp[(size_t)(n0 + i) * Ed + k0 + tx] = __float2half_rn(t[tx][i]);
    } else {
        // ---- mask bit-pack with inline dtype detection ----
        if (tid < 5) cnt[tid] = 0;
        __syncthreads();
        {
            const unsigned char* m8 = (const unsigned char*)mask;
            int loc[5] = {0, 0, 0, 0, 0};
            for (int i = tid; i < 16384; i += 256) {
                unsigned char v = m8[i];
                if (v) { loc[i & 3]++; if (v != 1) loc[4]++; }
            }
#pragma unroll
            for (int j = 0; j < 5; j++) if (loc[j]) atomicAdd(&cnt[j], loc[j]);
        }
        __syncthreads();
        int mode;
        {
            int c0 = cnt[0], c1 = cnt[1], c2 = cnt[2], c3 = cnt[3], weird = cnt[4];
            if (c1 == 0 && c2 == 0 && c3 == 0) mode = 1;       // int32
            else if (c0 == 0 && c1 == 0)       mode = 2;       // float32
            else if (weird > 0)                mode = 3;       // 16-bit
            else                               mode = 0;       // bytes
        }
        int w = (bz - (F2H_BLKS + TRW_BLKS + TRF_BLKS)) * 256 + tid;
        unsigned long long bits = 0;
        if (mode == 0) {
            const uint4* p = (const uint4*)((const unsigned char*)mask + (size_t)w * 64);
#pragma unroll
            for (int i = 0; i < 4; i++) {
                uint4 v = p[i];
                uint32_t ws[4] = {v.x, v.y, v.z, v.w};
#pragma unroll
                for (int j = 0; j < 4; j++)
#pragma unroll
                    for (int bq = 0; bq < 4; bq++)
                        if ((ws[j] >> (8 * bq)) & 0xFFu)
                            bits |= 1ull << (i * 16 + j * 4 + bq);
            }
        } else if (mode == 1 || mode == 2) {
            const uint4* p = (const uint4*)((const uint32_t*)mask + (size_t)w * 64);
#pragma unroll
            for (int i = 0; i < 16; i++) {
                uint4 v = p[i];
                if (v.x) bits |= 1ull << (i * 4 + 0);
                if (v.y) bits |= 1ull << (i * 4 + 1);
                if (v.z) bits |= 1ull << (i * 4 + 2);
                if (v.w) bits |= 1ull << (i * 4 + 3);
            }
        } else {
            const uint4* p = (const uint4*)((const unsigned short*)mask + (size_t)w * 64);
#pragma unroll
            for (int i = 0; i < 8; i++) {
                uint4 v = p[i];
                uint32_t ws[4] = {v.x, v.y, v.z, v.w};
#pragma unroll
                for (int j = 0; j < 4; j++) {
                    if (ws[j] & 0xFFFFu) bits |= 1ull << (i * 8 + j * 2);
                    if (ws[j] >> 16)     bits |= 1ull << (i * 8 + j * 2 + 1);
                }
            }
        }
        mbits[w] = bits;
    }
}

// ---------------- fp16 mma.sync GEMM with ldmatrix fragments (proven R9) -----
#define GLD 40
#define GBK 32

template<int MODE>
__global__ __launch_bounds__(256, 2)
void hgemm_k(const __half* __restrict__ A, const __half* __restrict__ Bt,
             const float* __restrict__ bias, float* __restrict__ C,
             __half* __restrict__ qh2, __half* __restrict__ kh2,
             __half* __restrict__ vh, int N, int K)
{
    __shared__ __half As[2][128 * GLD];
    __shared__ __half Bs[2][128 * GLD];

    const int tid = threadIdx.x;
    const int warp = tid >> 5, lane = tid & 31;
    const int gid = lane >> 2, tig = lane & 3;
    const int lr = lane & 7, lq = lane >> 3;
    const int m0 = blockIdx.y * 128, n0 = blockIdx.x * 128;
    const int wm0 = (warp & 3) * 32;
    const int wn0 = (warp >> 2) * 64;

    const __half* Ab = A + (size_t)m0 * K;
    const __half* Bb = Bt + (size_t)n0 * K;

    float acc[2][8][4];
#pragma unroll
    for (int i = 0; i < 2; i++)
#pragma unroll
        for (int j = 0; j < 8; j++)
#pragma unroll
            for (int r = 0; r < 4; r++) acc[i][j][r] = 0.f;

    const int lr0 = tid >> 2,          lc0 = (tid & 3) * 8;
    const int lr1 = (tid + 256) >> 2,  lc1 = (tid & 3) * 8;

    const int NS = K / GBK;

    {
        uint32_t asb = smem_u32(&As[0][0]);
        uint32_t bsb = smem_u32(&Bs[0][0]);
        cp_async16(asb + (lr0 * GLD + lc0) * 2, Ab + (size_t)lr0 * K + lc0);
        cp_async16(asb + (lr1 * GLD + lc1) * 2, Ab + (size_t)lr1 * K + lc1);
        cp_async16(bsb + (lr0 * GLD + lc0) * 2, Bb + (size_t)lr0 * K + lc0);
        cp_async16(bsb + (lr1 * GLD + lc1) * 2, Bb + (size_t)lr1 * K + lc1);
        CP_COMMIT();
    }

    const int a_row_off = (lq & 1) * 8 + lr;
    const int a_col_off = (lq >> 1) * 8;
    const int b_row_off = (lq >> 1) * 8 + lr;
    const int b_col_off = (lq & 1) * 8;

    for (int s = 0; s < NS; ++s) {
        if (s + 1 < NS) {
            int buf = (s + 1) & 1;
            int kb = (s + 1) * GBK;
            uint32_t asb = smem_u32(&As[buf][0]);
            uint32_t bsb = smem_u32(&Bs[buf][0]);
            cp_async16(asb + (lr0 * GLD + lc0) * 2, Ab + (size_t)lr0 * K + kb + lc0);
            cp_async16(asb + (lr1 * GLD + lc1) * 2, Ab + (size_t)lr1 * K + kb + lc1);
            cp_async16(bsb + (lr0 * GLD + lc0) * 2, Bb + (size_t)lr0 * K + kb + lc0);
            cp_async16(bsb + (lr1 * GLD + lc1) * 2, Bb + (size_t)lr1 * K + kb + lc1);
            CP_COMMIT();
            CP_WAIT(1);
        } else {
            CP_WAIT(0);
        }
        __syncthreads();

        uint32_t asb = smem_u32(&As[s & 1][0]);
        uint32_t bsb = smem_u32(&Bs[s & 1][0]);
#pragma unroll
        for (int kk = 0; kk < GBK; kk += 16) {
            uint32_t afr[2][4];
#pragma unroll
            for (int i = 0; i < 2; i++) {
                uint32_t addr = asb + ((wm0 + 16 * i + a_row_off) * GLD + kk + a_col_off) * 2;
                LDM_X4(afr[i][0], afr[i][1], afr[i][2], afr[i][3], addr);
            }
            uint32_t bfr[8][2];
#pragma unroll
            for (int jj = 0; jj < 8; jj += 2) {
                uint32_t addr = bsb + ((wn0 + 8 * jj + b_row_off) * GLD + kk + b_col_off) * 2;
                LDM_X4(bfr[jj][0], bfr[jj][1], bfr[jj + 1][0], bfr[jj + 1][1], addr);
            }
#pragma unroll
            for (int j = 0; j < 8; j++) {
                mma_f16(acc[0][j], afr[0], bfr[j][0], bfr[j][1]);
                mma_f16(acc[1][j], afr[1], bfr[j][0], bfr[j][1]);
            }
        }
        __syncthreads();
    }

#pragma unroll
    for (int i = 0; i < 2; i++) {
        int row = m0 + wm0 + 16 * i + gid;
#pragma unroll
        for (int j = 0; j < 8; j++) {
            int col = n0 + wn0 + 8 * j + 2 * tig;
            float2 bv = *(const float2*)&bias[col];
            float v00 = acc[i][j][0] + bv.x, v01 = acc[i][j][1] + bv.y;
            float v10 = acc[i][j][2] + bv.x, v11 = acc[i][j][3] + bv.y;
            if (MODE == 0) {
                float2 o0, o1;
                o0.x = v00; o0.y = v01; o1.x = v10; o1.y = v11;
                *(float2*)&C[(size_t)row * N + col]       = o0;
                *(float2*)&C[(size_t)(row + 8) * N + col] = o1;
            } else {
                int lc = col & 1023;
                if (col < Ed) {
                    *(uint32_t*)&qh2[(size_t)row * Ed + lc] =
                        pack_h2(v00 * QSCALE, v01 * QSCALE);
                    *(uint32_t*)&qh2[(size_t)(row + 8) * Ed + lc] =
                        pack_h2(v10 * QSCALE, v11 * QSCALE);
                } else if (col < 2 * Ed) {
                    *(uint32_t*)&kh2[(size_t)row * Ed + lc]       = pack_h2(v00, v01);
                    *(uint32_t*)&kh2[(size_t)(row + 8) * Ed + lc] = pack_h2(v10, v11);
                } else {
                    *(uint32_t*)&vh[(size_t)row * Ed + lc]       = pack_h2(v00, v01);
                    *(uint32_t*)&vh[(size_t)(row + 8) * Ed + lc] = pack_h2(v10, v11);
                }
            }
        }
    }
}

// ---------------- fp16 flash attention v5 (V via ldmatrix.trans) ------------
#define LK 72
#define KH_BYTES (64 * LK * 2)             // 9216
#define QH_BYTES (128 * LK * 2)            // 18432
#define AT_SMEM (QH_BYTES + 4 * KH_BYTES)  // 55296

__global__ __launch_bounds__(256, 2)
void attention_f16_kernel(const __half* __restrict__ qh2,
                          const __half* __restrict__ kh2,
                          const __half* __restrict__ vh,
                          const unsigned long long* __restrict__ mbits,
                          __half* __restrict__ ctxh) {
    extern __shared__ char asmem[];
    const uint32_t qh_smb = smem_u32(asmem);
    const uint32_t kh_smb = qh_smb + QH_BYTES;
    const uint32_t vs_smb = kh_smb + 2 * KH_BYTES;
    const __half* QHs = (const __half*)asmem;

    const int qt = blockIdx.x, bh = blockIdx.y;
    const int b = bh >> 4, h = bh & 15;
    const int tid = threadIdx.x, lane = tid & 31, warp = tid >> 5;
    const int gid = lane >> 2, tig = lane & 3;
    const int lr = lane & 7, lq = lane >> 3;
    const int q0 = qt * 128, hoff = h * Dh;
    const size_t bS = (size_t)b * Sq;
    const int wrow = warp * 16;
    const int r0 = wrow + gid, r1 = r0 + 8;

    // K tile ([key n][d k], row-major -> B frag non-trans):
    const uint32_t k_ldm_off = (lr * LK + 8 * lq) * 2;
    // V tile ([s k][d n], row-major -> B frag via trans; per-lane like GEMM-A):
    const uint32_t v_ldm_off = (((lq & 1) * 8 + lr) * LK + (lq >> 1) * 8) * 2;

    // prologue: Q tile + K/V tile 0, one cp.async group
#pragma unroll
    for (int t = 0; t < 4; t++) {
        int idx = tid + t * 256;
        int r = idx >> 3, c = (idx & 7) * 8;
        cp_async16(qh_smb + (r * LK + c) * 2, qh2 + (bS + q0 + r) * Ed + hoff + c);
    }
#pragma unroll
    for (int t = 0; t < 2; t++) {
        int idx = tid + t * 256;
        int r = idx >> 3, c = (idx & 7) * 8;
        cp_async16(kh_smb + (r * LK + c) * 2, kh2 + (bS + r) * Ed + hoff + c);
        cp_async16(vs_smb + (r * LK + c) * 2, vh  + (bS + r) * Ed + hoff + c);
    }
    CP_COMMIT();
    CP_WAIT(0);
    __syncthreads();

    // Q fragments (pre-scaled fp16)
    uint32_t qf[4][4];
#pragma unroll
    for (int kc = 0; kc < 4; kc++) {
        qf[kc][0] = *(const uint32_t*)&QHs[r0 * LK + 16 * kc + 2 * tig];
        qf[kc][1] = *(const uint32_t*)&QHs[r1 * LK + 16 * kc + 2 * tig];
        qf[kc][2] = *(const uint32_t*)&QHs[r0 * LK + 16 * kc + 8 + 2 * tig];
        qf[kc][3] = *(const uint32_t*)&QHs[r1 * LK + 16 * kc + 8 + 2 * tig];
    }

    const unsigned long long* mr0 = mbits + (bS + q0 + r0) * (Sq / 64);
    const unsigned long long* mr1 = mbits + (bS + q0 + r1) * (Sq / 64);

    float oacc[8][4], osum[4];
#pragma unroll
    for (int j = 0; j < 8; j++)
#pragma unroll
        for (int r = 0; r < 4; r++) oacc[j][r] = 0.f;
#pragma unroll
    for (int r = 0; r < 4; r++) osum[r] = 0.f;

    const uint32_t ONES = 0x3C003C00u;

    for (int kt = 0; kt < Sq / 64; kt++) {
        const int buf = kt & 1;
        __syncthreads();
        if (kt + 1 < Sq / 64) {
            int k0n = (kt + 1) * 64;
            uint32_t kb = kh_smb + (buf ^ 1) * KH_BYTES;
            uint32_t vb = vs_smb + (buf ^ 1) * KH_BYTES;
#pragma unroll
            for (int t = 0; t < 2; t++) {
                int idx = tid + t * 256;
                int r = idx >> 3, c = (idx & 7) * 8;
                cp_async16(kb + (r * LK + c) * 2, kh2 + (bS + k0n + r) * Ed + hoff + c);
                cp_async16(vb + (r * LK + c) * 2, vh  + (bS + k0n + r) * Ed + hoff + c);
            }
            CP_COMMIT();
            CP_WAIT(1);
        } else {
            CP_WAIT(0);
        }
        __syncthreads();

        const uint32_t kbase = kh_smb + buf * KH_BYTES + k_ldm_off;
        const uint32_t vbase = vs_smb + buf * KH_BYTES + v_ldm_off;

        unsigned long long mb0 = mr0[kt];
        unsigned long long mb1 = mr1[kt];

        // QK^T via ldmatrix.x4 B-fragments
        float sc[8][4];
#pragma unroll
        for (int j = 0; j < 8; j++)
#pragma unroll
            for (int r = 0; r < 4; r++) sc[j][r] = 0.f;
#pragma unroll
        for (int j = 0; j < 8; j++) {
            uint32_t kaddr = kbase + j * (8 * LK * 2);
            uint32_t k0r, k1r, k2r, k3r, k4r, k5r, k6r, k7r;
            LDM_X4(k0r, k1r, k2r, k3r, kaddr);
            LDM_X4(k4r, k5r, k6r, k7r, kaddr + 64);
            mma_f16(sc[j], qf[0], k0r, k1r);
            mma_f16(sc[j], qf[1], k2r, k3r);
            mma_f16(sc[j], qf[2], k4r, k5r);
            mma_f16(sc[j], qf[3], k6r, k7r);
        }

        // mask quirk + clamp + fp16 pack + 2^y
        uint32_t pp[8][2];
#pragma unroll
        for (int j = 0; j < 8; j++) {
            int col = 8 * j + 2 * tig;
            float y00 = ((mb0 >> col) & 1)       ? MASKC : fminf(sc[j][0], 14.f);
            float y01 = ((mb0 >> (col + 1)) & 1) ? MASKC : fminf(sc[j][1], 14.f);
            float y10 = ((mb1 >> col) & 1)       ? MASKC : fminf(sc[j][2], 14.f);
            float y11 = ((mb1 >> (col + 1)) & 1) ? MASKC : fminf(sc[j][3], 14.f);
            pp[j][0] = ex2_h2(pack_h2(y00, y01));
            pp[j][1] = ex2_h2(pack_h2(y10, y11));
        }

        // PV (+ ones-column denominator) via ldmatrix.x4.trans V fragments
#pragma unroll
        for (int kc = 0; kc < 4; kc++) {
            uint32_t a[4] = { pp[2 * kc][0], pp[2 * kc][1],
                              pp[2 * kc + 1][0], pp[2 * kc + 1][1] };
            mma_f16(osum, a, ONES, ONES);
#pragma unroll
            for (int jj = 0; jj < 8; jj += 2) {
                uint32_t b0, b1, b2, b3;
                LDM_X4_T(b0, b1, b2, b3,
                         vbase + (16 * kc * LK + 8 * jj) * 2);
                mma_f16(oacc[jj],     a, b0, b1);
                mma_f16(oacc[jj + 1], a, b2, b3);
            }
        }
    }

    // epilogue: normalize by ones-MMA rowsums, write ctx fp16
    float inv0 = 1.f / osum[0], inv1 = 1.f / osum[2];
    const size_t row0 = bS + q0 + wrow + gid;
#pragma unroll
    for (int j = 0; j < 8; j++) {
        int col = hoff + 8 * j + 2 * tig;
        *(uint32_t*)&ctxh[row0 * Ed + col] =
            pack_h2(oacc[j][0] * inv0, oacc[j][1] * inv0);
        *(uint32_t*)&ctxh[(row0 + 8) * Ed + col] =
            pack_h2(oacc[j][2] * inv1, oacc[j][3] * inv1);
    }
}

// ---------------- launcher ----------------
extern "C" void kernel_launch(void* const* d_in, const int* in_sizes, int n_in,
                              void* d_out, int out_size) {
    const float* x        = (const float*)d_in[0];
    const void*  amask    = d_in[1];
    const float* w_kernel = (const float*)d_in[2];
    const float* w_bias   = (const float*)d_in[3];
    const float* fc_kernel= (const float*)d_in[4];
    const float* fc_bias  = (const float*)d_in[5];
    float* out = (float*)d_out;

    __half *xh, *wh, *w2h, *qh2, *kh2, *vh, *ctxh;
    unsigned long long* mbits;
    cudaGetSymbolAddress((void**)&xh,   g_xh);
    cudaGetSymbolAddress((void**)&wh,   g_wh);
    cudaGetSymbolAddress((void**)&w2h,  g_w2h);
    cudaGetSymbolAddress((void**)&qh2,  g_qh2);
    cudaGetSymbolAddress((void**)&kh2,  g_kh2);
    cudaGetSymbolAddress((void**)&vh,   g_vh);
    cudaGetSymbolAddress((void**)&ctxh, g_ctxh);
    cudaGetSymbolAddress((void**)&mbits, g_mbits);

    // 1. fused prep: x->fp16, w^T->fp16, fc^T->fp16, mask bit-pack
    prep_all_kernel<<<PREP_BLKS, 256>>>((const float4*)x, w_kernel, fc_kernel,
                                        amask, (uint2*)xh, wh, w2h, mbits);

    // 2. QKV projection with fused fp16 split epilogue
    hgemm_k<1><<<dim3(E3 / 128, Mrows / 128), 256>>>(
        xh, wh, w_bias, nullptr, qh2, kh2, vh, E3, Ed);

    // 3. fp16 flash attention (V transposed on the fly via ldmatrix.trans)
    {
        cudaFuncSetAttribute(attention_f16_kernel,
                             cudaFuncAttributeMaxDynamicSharedMemorySize, AT_SMEM);
        dim3 grid(Sq / 128, Bz * Hh);
        attention_f16_kernel<<<grid, 256, AT_SMEM>>>(qh2, kh2, vh, mbits, ctxh);
    }

    // 4. output projection
    hgemm_k<0><<<dim3(Ed / 128, Mrows / 128), 256>>>(
        ctxh, w2h, fc_bias, out, nullptr, nullptr, nullptr, Ed, Ed);
}